// round 9
// baseline (speedup 1.0000x reference)
#include <cuda_runtime.h>
#include <cuda_fp16.h>
#include <cstdint>
#include <math.h>

#define BB 8
#define NN 89
#define CC 1024
#define HH 512
#define M_EDGE (BB*NN*NN)   // 63368

// Scratch
__device__ __half g_p [(size_t)M_EDGE * CC];   // 130 MB
__device__ __half g_h1[(size_t)M_EDGE * CC];   // 130 MB
__device__ float  g_spart[(size_t)8 * M_EDGE]; // s partial sums [8][M]
__device__ __half g_wt1[CC*CC];                // Wa1^T [1024,1024]
__device__ __half g_wt2[HH*CC];                // Wa2^T [512,1024]
__device__ float g_at[BB*NN*CC];
__device__ float g_mt[BB*NN*CC];
__device__ float g_t1a[BB*NN*CC];
__device__ float g_t1m[BB*NN*CC];

// ---------------------------------------------------------------------------
__device__ __forceinline__ unsigned f2tf32(float x){
    unsigned r; asm("cvt.rna.tf32.f32 %0, %1;" : "=r"(r) : "f"(x)); return r;
}
__device__ __forceinline__ float4 round4(float4 v){
    return make_float4(__uint_as_float(f2tf32(v.x)), __uint_as_float(f2tf32(v.y)),
                       __uint_as_float(f2tf32(v.z)), __uint_as_float(f2tf32(v.w)));
}
__device__ __forceinline__ uint32_t smem_u32(const void* p){
    uint32_t a;
    asm("{ .reg .u64 t; cvta.to.shared.u64 t, %1; cvt.u32.u64 %0, t; }" : "=r"(a) : "l"(p));
    return a;
}
__device__ __forceinline__ void hmma(float c[4], const uint32_t a[4], const uint32_t b[2]){
    asm volatile("mma.sync.aligned.m16n8k16.row.col.f32.f16.f16.f32 "
        "{%0,%1,%2,%3}, {%4,%5,%6,%7}, {%8,%9}, {%0,%1,%2,%3};"
        : "+f"(c[0]), "+f"(c[1]), "+f"(c[2]), "+f"(c[3])
        : "r"(a[0]), "r"(a[1]), "r"(a[2]), "r"(a[3]), "r"(b[0]), "r"(b[1]));
}
__device__ __forceinline__ void ldmx4(uint32_t a[4], uint32_t addr){
    asm volatile("ldmatrix.sync.aligned.m8n8.x4.shared.b16 {%0,%1,%2,%3}, [%4];"
        : "=r"(a[0]), "=r"(a[1]), "=r"(a[2]), "=r"(a[3]) : "r"(addr));
}
__device__ __forceinline__ uint32_t pack_half2(float a, float b){
    __half2 h = __floats2half2_rn(a, b);
    return *reinterpret_cast<uint32_t*>(&h);
}
__device__ __forceinline__ void cp16(uint32_t dst, const void* src){
    asm volatile("cp.async.cg.shared.global [%0], [%1], 16;" :: "r"(dst), "l"(src));
}
__device__ __forceinline__ void cp_commit(){ asm volatile("cp.async.commit_group;"); }
template<int NW> __device__ __forceinline__ void cp_wait(){
    asm volatile("cp.async.wait_group %0;" :: "n"(NW));
}

// ---------------------------------------------------------------------------
// p[row,:] = half( x[b,j,:] * x[b,i,:] )
// ---------------------------------------------------------------------------
__global__ void __launch_bounds__(256) prod_kernel(const float* __restrict__ x, __half* __restrict__ p){
    const int row = blockIdx.x, seg = threadIdx.x;
    int b = row / (NN*NN), rem = row - b*(NN*NN), j = rem / NN, i = rem - j*NN;
    const float4 vj = ((const float4*)(x + (size_t)(b*NN + j)*CC))[seg];
    const float4 vi = ((const float4*)(x + (size_t)(b*NN + i)*CC))[seg];
    uint2 pk = make_uint2(pack_half2(vj.x*vi.x, vj.y*vi.y),
                          pack_half2(vj.z*vi.z, vj.w*vi.w));
    ((uint2*)p)[(size_t)row * 256 + seg] = pk;
}

// ---------------------------------------------------------------------------
// Wt[n,k] = half( W[k,n] )
// ---------------------------------------------------------------------------
__global__ void transpose_half(const float* __restrict__ W, __half* __restrict__ Wt, int K, int N){
    __shared__ float tile[32][33];
    int k0 = blockIdx.x*32, n0 = blockIdx.y*32;
    int tx = threadIdx.x, ty = threadIdx.y;
    #pragma unroll
    for (int r = 0; r < 32; r += 8)
        tile[ty + r][tx] = W[(size_t)(k0 + ty + r)*N + n0 + tx];
    __syncthreads();
    #pragma unroll
    for (int r = 0; r < 32; r += 8)
        Wt[(size_t)(n0 + ty + r)*K + k0 + tx] = __float2half(tile[tx][ty + r]);
}

// ---------------------------------------------------------------------------
// FP16 HMMA GEMM v4:  CTA 128x128, 4 warps (warp tile 64x64), BK=64,
// 3-stage cp.async, 2 CTAs/SM for cross-CTA latency hiding.
//   MODE 1: C half = relu(acc+bias)
//   MODE 2: no C; spart[col][r] = dot(relu(acc+bias), wvec)
// ---------------------------------------------------------------------------
#define LDH 72
#define BK 64
#define A_STAGE (128*LDH)   // halfs
#define B_STAGE (128*LDH)   // halfs

template<int MODE>
__global__ void __launch_bounds__(128, 2) hgemm(
    const __half* __restrict__ A, const __half* __restrict__ Bt,
    const float* __restrict__ bias, void* __restrict__ Cout,
    const float* __restrict__ wvec, float* __restrict__ spart,
    int M, int K, int N)
{
    extern __shared__ __half sh[];
    __half* Abase = sh;
    __half* Bbase = sh + 3*A_STAGE;

    const int t = threadIdx.x, warp = t >> 5, lane = t & 31;
    const int g = lane >> 2, tig = lane & 3;
    const int wm = (warp >> 1) * 64, wn = (warp & 1) * 64;
    const int mBase = blockIdx.y * 128, nBase = blockIdx.x * 128;

    // staging: thread t owns row t of both tiles (128 rows, 64 halfs = 8 cp16)
    int garow = mBase + t; if (garow >= M) garow = M - 1;   // clamp
    const __half* agp = A + (size_t)garow * K;
    const uint32_t aDst0 = smem_u32(Abase) + (uint32_t)(t * LDH * 2);
    const __half* bgp = Bt + (size_t)(nBase + t) * K;
    const uint32_t bDst0 = smem_u32(Bbase) + (uint32_t)(t * LDH * 2);

    const uint32_t uA = smem_u32(Abase);
    const uint32_t uB = smem_u32(Bbase);
    const int laneR = lane & 15, laneK = (lane >> 4) << 3;
    const int bg4 = lane >> 3, br = lane & 7;

    auto issue = [&](int kt){
        const int s = kt % 3;
        const int k0 = kt * BK;
        uint32_t da = aDst0 + (uint32_t)(s * A_STAGE * 2);
        uint32_t db = bDst0 + (uint32_t)(s * B_STAGE * 2);
        #pragma unroll
        for (int q = 0; q < 8; q++) cp16(da + q*16, agp + k0 + q*8);
        #pragma unroll
        for (int q = 0; q < 8; q++) cp16(db + q*16, bgp + k0 + q*8);
    };

    float acc[4][8][4];
    #pragma unroll
    for (int mi = 0; mi < 4; mi++)
        #pragma unroll
        for (int ni = 0; ni < 8; ni++)
            #pragma unroll
            for (int q = 0; q < 4; q++) acc[mi][ni][q] = 0.f;

    const int KT = K / BK;   // 16
    issue(0); cp_commit();
    issue(1); cp_commit();

    for (int kt = 0; kt < KT; kt++){
        cp_wait<1>();
        __syncthreads();
        if (kt + 2 < KT) issue(kt + 2);
        cp_commit();

        const int s = kt % 3;
        const uint32_t uAs = uA + (uint32_t)(s * A_STAGE * 2);
        const uint32_t uBs = uB + (uint32_t)(s * B_STAGE * 2);

        #pragma unroll
        for (int ko = 0; ko < BK; ko += 16){
            uint32_t af[4][4], bf[8][2];
            #pragma unroll
            for (int mi = 0; mi < 4; mi++)
                ldmx4(af[mi], uAs + (uint32_t)(((wm + mi*16 + laneR)*LDH + ko + laneK) * 2));
            #pragma unroll
            for (int nq = 0; nq < 4; nq++){
                uint32_t r4[4];
                int n = wn + nq*16 + (bg4 >> 1)*8 + br;
                int k = ko + (bg4 & 1)*8;
                ldmx4(r4, uBs + (uint32_t)((n*LDH + k) * 2));
                bf[nq*2  ][0] = r4[0]; bf[nq*2  ][1] = r4[1];
                bf[nq*2+1][0] = r4[2]; bf[nq*2+1][1] = r4[3];
            }
            #pragma unroll
            for (int mi = 0; mi < 4; mi++)
                #pragma unroll
                for (int ni = 0; ni < 8; ni++)
                    hmma(acc[mi][ni], af[mi], bf[ni]);
        }
    }

    // ---- epilogue ----
    if (MODE == 1){
        #pragma unroll
        for (int mi = 0; mi < 4; mi++)
            #pragma unroll
            for (int ni = 0; ni < 8; ni++){
                const int cb = nBase + wn + ni*8 + 2*tig;
                const float2 bs = *(const float2*)(bias + cb);
                #pragma unroll
                for (int hh = 0; hh < 2; hh++){
                    const int r = mBase + wm + mi*16 + g + hh*8;
                    if (r >= M) continue;
                    float z0 = fmaxf(acc[mi][ni][hh*2+0] + bs.x, 0.f);
                    float z1 = fmaxf(acc[mi][ni][hh*2+1] + bs.y, 0.f);
                    *(uint32_t*)((__half*)Cout + (size_t)r * N + cb) = pack_half2(z0, z1);
                }
            }
    } else {
        float rs[4][2];
        #pragma unroll
        for (int mi = 0; mi < 4; mi++){ rs[mi][0] = 0.f; rs[mi][1] = 0.f; }
        #pragma unroll
        for (int mi = 0; mi < 4; mi++)
            #pragma unroll
            for (int ni = 0; ni < 8; ni++){
                const int cb = nBase + wn + ni*8 + 2*tig;
                const float2 bs = *(const float2*)(bias + cb);
                const float2 wv = *(const float2*)(wvec + cb);
                #pragma unroll
                for (int hh = 0; hh < 2; hh++){
                    float z0 = fmaxf(acc[mi][ni][hh*2+0] + bs.x, 0.f);
                    float z1 = fmaxf(acc[mi][ni][hh*2+1] + bs.y, 0.f);
                    rs[mi][hh] += z0*wv.x + z1*wv.y;
                }
            }
        const int col = blockIdx.x * 2 + (warp & 1);
        #pragma unroll
        for (int mi = 0; mi < 4; mi++)
            #pragma unroll
            for (int hh = 0; hh < 2; hh++){
                float v = rs[mi][hh];
                v += __shfl_xor_sync(0xffffffffu, v, 1);
                v += __shfl_xor_sync(0xffffffffu, v, 2);
                const int r = mBase + wm + mi*16 + g + hh*8;
                if (tig == 0 && r < M)
                    spart[(size_t)col * M + r] = v;
            }
    }
}

// ---------------------------------------------------------------------------
// legacy tf32 GEMM for small 712-row GEMMs; blockIdx.z merges the layer-1 pair
// ---------------------------------------------------------------------------
__device__ __forceinline__ void mma_frag(float c[4], const unsigned a[4], const unsigned b[2]){
    asm volatile("mma.sync.aligned.m16n8k8.row.col.f32.tf32.tf32.f32 "
        "{%0,%1,%2,%3}, {%4,%5,%6,%7}, {%8,%9}, {%0,%1,%2,%3};\n"
        : "+f"(c[0]), "+f"(c[1]), "+f"(c[2]), "+f"(c[3])
        : "r"(a[0]), "r"(a[1]), "r"(a[2]), "r"(a[3]), "r"(b[0]), "r"(b[1]));
}
__global__ void __launch_bounds__(256) mma_gemm(
    const float* __restrict__ A0, const float* __restrict__ A1,
    const float* __restrict__ B0, const float* __restrict__ B1,
    const float* __restrict__ bias0, const float* __restrict__ bias1,
    float* __restrict__ C0, float* __restrict__ C1,
    const float* __restrict__ aux, int M, int K, int Ncols, int mode)
{
    const float* A    = blockIdx.z ? A1 : A0;
    const float* Bm   = blockIdx.z ? B1 : B0;
    const float* bias = blockIdx.z ? bias1 : bias0;
    float* Cmat       = blockIdx.z ? C1 : C0;

    __shared__ __align__(16) float As[2][16][136];
    __shared__ __align__(16) float Bs[2][16][136];
    const int t = threadIdx.x, warp = t >> 5, lane = t & 31;
    const int g = lane >> 2, tig = lane & 3;
    const int wm = (warp >> 2) * 64, wn = (warp & 3) * 32;
    const int mBase = blockIdx.y * 128, nBase = blockIdx.x * 128;
    const int arow = t >> 2, akq = (t & 3) * 4;
    const int grow0 = mBase + arow, grow1 = grow0 + 64;
    const bool v0 = grow0 < M, v1 = grow1 < M;
    const float* ap0 = v0 ? A + (size_t)grow0 * K : nullptr;
    const float* ap1 = v1 ? A + (size_t)grow1 * K : nullptr;
    const int bkr = t >> 5, bnc = (t & 31) * 4;
    float4 a0s, a1s, b0s, b1s;
    auto load_g = [&](int k0){
        const float4 z = make_float4(0,0,0,0);
        a0s = v0 ? *(const float4*)(ap0 + k0 + akq) : z;
        a1s = v1 ? *(const float4*)(ap1 + k0 + akq) : z;
        b0s = *(const float4*)(Bm + (size_t)(k0 + bkr    ) * Ncols + nBase + bnc);
        b1s = *(const float4*)(Bm + (size_t)(k0 + bkr + 8) * Ncols + nBase + bnc);
    };
    auto store_s = [&](int buf){
        float4 c0 = round4(a0s), c1 = round4(a1s);
        As[buf][akq+0][arow] = c0.x; As[buf][akq+1][arow] = c0.y;
        As[buf][akq+2][arow] = c0.z; As[buf][akq+3][arow] = c0.w;
        As[buf][akq+0][arow+64] = c1.x; As[buf][akq+1][arow+64] = c1.y;
        As[buf][akq+2][arow+64] = c1.z; As[buf][akq+3][arow+64] = c1.w;
        *(float4*)&Bs[buf][bkr][bnc]     = round4(b0s);
        *(float4*)&Bs[buf][bkr + 8][bnc] = round4(b1s);
    };
    float acc[4][4][4];
    #pragma unroll
    for (int mi = 0; mi < 4; mi++)
        #pragma unroll
        for (int ni = 0; ni < 4; ni++)
            #pragma unroll
            for (int q = 0; q < 4; q++) acc[mi][ni][q] = 0.f;
    load_g(0); store_s(0); __syncthreads();
    const int KT = K / 16;
    for (int kt = 0; kt < KT; kt++){
        const int cur = kt & 1;
        if (kt + 1 < KT) load_g((kt + 1) * 16);
        #pragma unroll
        for (int ko = 0; ko < 16; ko += 8){
            unsigned af[4][4], bf[4][2];
            #pragma unroll
            for (int mi = 0; mi < 4; mi++){
                const int m0 = wm + mi*16 + g;
                af[mi][0] = __float_as_uint(As[cur][ko + tig    ][m0    ]);
                af[mi][1] = __float_as_uint(As[cur][ko + tig    ][m0 + 8]);
                af[mi][2] = __float_as_uint(As[cur][ko + tig + 4][m0    ]);
                af[mi][3] = __float_as_uint(As[cur][ko + tig + 4][m0 + 8]);
            }
            #pragma unroll
            for (int ni = 0; ni < 4; ni++){
                const int n0 = wn + ni*8 + g;
                bf[ni][0] = __float_as_uint(Bs[cur][ko + tig    ][n0]);
                bf[ni][1] = __float_as_uint(Bs[cur][ko + tig + 4][n0]);
            }
            #pragma unroll
            for (int mi = 0; mi < 4; mi++)
                #pragma unroll
                for (int ni = 0; ni < 4; ni++)
                    mma_frag(acc[mi][ni], af[mi], bf[ni]);
        }
        if (kt + 1 < KT) store_s((kt + 1) & 1);
        __syncthreads();
    }
    #pragma unroll
    for (int mi = 0; mi < 4; mi++)
        #pragma unroll
        for (int ni = 0; ni < 4; ni++){
            const int cb = nBase + wn + ni*8 + 2*tig;
            const float2 bs = *(const float2*)(bias + cb);
            #pragma unroll
            for (int hh = 0; hh < 2; hh++){
                const int r = mBase + wm + mi*16 + g + hh*8;
                if (r >= M) continue;
                float z0 = acc[mi][ni][hh*2+0] + bs.x;
                float z1 = acc[mi][ni][hh*2+1] + bs.y;
                if (mode == 0){ z0 = fmaxf(z0, 0.f); z1 = fmaxf(z1, 0.f); }
                else {
                    const float2 a = *(const float2*)(aux + (size_t)r * Ncols + cb);
                    z0 += a.x; z1 += a.y;
                    if (mode == 2){ z0 *= (1.f/3.f); z1 *= (1.f/3.f); }
                }
                *(float2*)(Cmat + (size_t)r * Ncols + cb) = make_float2(z0, z1);
            }
        }
}

// ---------------------------------------------------------------------------
// aggregation with fused s finalize
// ---------------------------------------------------------------------------
__global__ void __launch_bounds__(256) agg_kernel(
    const float* __restrict__ x, const float* __restrict__ spart,
    const float* __restrict__ ba3,
    const float* __restrict__ adj_add, const float* __restrict__ adj_mod,
    float* __restrict__ at, float* __restrict__ mt)
{
    __shared__ float sv_sh[NN];
    int bi = blockIdx.x;
    int b = bi / NN, i = bi - b*NN;
    if (threadIdx.x < NN){
        int row = (b*NN + threadIdx.x)*NN + i;
        float v = ba3[0];
        #pragma unroll
        for (int c = 0; c < 8; c++) v += spart[(size_t)c * M_EDGE + row];
        sv_sh[threadIdx.x] = 1.f / (1.f + expf(-v));
    }
    __syncthreads();

    int f = threadIdx.x * 4;
    float4 aa = make_float4(0,0,0,0), mm = make_float4(0,0,0,0);
    for (int j = 0; j < NN; j++){
        float wa = sv_sh[j] * adj_add[j*NN + i];
        float wm = adj_mod[j*NN + i];
        float4 xv = *(const float4*)(x + (size_t)(b*NN + j)*CC + f);
        aa.x = fmaf(wa, xv.x, aa.x); aa.y = fmaf(wa, xv.y, aa.y);
        aa.z = fmaf(wa, xv.z, aa.z); aa.w = fmaf(wa, xv.w, aa.w);
        mm.x = fmaf(wm, xv.x, mm.x); mm.y = fmaf(wm, xv.y, mm.y);
        mm.z = fmaf(wm, xv.z, mm.z); mm.w = fmaf(wm, xv.w, mm.w);
    }
    float4 xv = *(const float4*)(x + (size_t)bi * CC + f);
    mm.x *= xv.x; mm.y *= xv.y; mm.z *= xv.z; mm.w *= xv.w;
    *(float4*)(at + (size_t)bi * CC + f) = aa;
    *(float4*)(mt + (size_t)bi * CC + f) = mm;
}

// ---------------------------------------------------------------------------
extern "C" void kernel_launch(void* const* d_in, const int* in_sizes, int n_in,
                              void* d_out, int out_size)
{
    const float* x    = (const float*)d_in[0];
    const float* Wa1  = (const float*)d_in[3];
    const float* ba1  = (const float*)d_in[4];
    const float* Wa2  = (const float*)d_in[5];
    const float* ba2  = (const float*)d_in[6];
    const float* Wa3  = (const float*)d_in[7];
    const float* ba3  = (const float*)d_in[8];
    float* out = (float*)d_out;

    __half *p, *h1, *wt1, *wt2;
    float *spart, *at, *mt, *t1a, *t1m;
    cudaGetSymbolAddress((void**)&p,    g_p);
    cudaGetSymbolAddress((void**)&h1,   g_h1);
    cudaGetSymbolAddress((void**)&spart,g_spart);
    cudaGetSymbolAddress((void**)&wt1,  g_wt1);
    cudaGetSymbolAddress((void**)&wt2,  g_wt2);
    cudaGetSymbolAddress((void**)&at,   g_at);
    cudaGetSymbolAddress((void**)&mt,   g_mt);
    cudaGetSymbolAddress((void**)&t1a,  g_t1a);
    cudaGetSymbolAddress((void**)&t1m,  g_t1m);

    const int M = M_EDGE, MR = BB * NN;
    const int MT = (M + 127) / 128;   // 496
    const int SMEM = 3 * (A_STAGE + B_STAGE) * 2;   // 110592 B

    cudaFuncSetAttribute(hgemm<1>, cudaFuncAttributeMaxDynamicSharedMemorySize, SMEM);
    cudaFuncSetAttribute(hgemm<2>, cudaFuncAttributeMaxDynamicSharedMemorySize, SMEM);

    // prep
    transpose_half<<<dim3(CC/32, CC/32), dim3(32,8)>>>(Wa1, wt1, CC, CC);
    transpose_half<<<dim3(CC/32, HH/32), dim3(32,8)>>>(Wa2, wt2, CC, HH);
    prod_kernel<<<M, 256>>>(x, p);

    // h1 = relu(p @ Wa1 + ba1)   [half out]
    hgemm<1><<<dim3(CC/128, MT), 128, SMEM>>>(p, wt1, ba1, h1, nullptr, nullptr, M, CC, CC);
    // s partials (h2 never materialized)
    hgemm<2><<<dim3(HH/128, MT), 128, SMEM>>>(h1, wt2, ba2, nullptr, Wa3, spart, M, CC, HH);

    agg_kernel<<<MR, 256>>>(x, spart, ba3, (const float*)d_in[1], (const float*)d_in[2], at, mt);

    const int MRT = (MR + 127) / 128; // 6
    mma_gemm<<<dim3(CC/128, MRT, 2), 256>>>(
        at, mt, (const float*)d_in[9], (const float*)d_in[13],
        (const float*)d_in[10], (const float*)d_in[14],
        t1a, t1m, nullptr, MR, CC, CC, 0);
    mma_gemm<<<dim3(CC/128, MRT, 1), 256>>>(
        t1a, nullptr, (const float*)d_in[11], nullptr,
        (const float*)d_in[12], nullptr,
        out, nullptr, x, MR, CC, CC, 1);
    mma_gemm<<<dim3(CC/128, MRT, 1), 256>>>(
        t1m, nullptr, (const float*)d_in[15], nullptr,
        (const float*)d_in[16], nullptr,
        out, nullptr, out, MR, CC, CC, 2);
}

// round 10
// speedup vs baseline: 1.7724x; 1.7724x over previous
#include <cuda_runtime.h>
#include <cuda_fp16.h>
#include <cstdint>
#include <math.h>

#define BB 8
#define NN 89
#define CC 1024
#define HH 512
#define TRI (NN*(NN+1)/2)        // 4005 unordered pairs (j<=i)
#define M_SYM (BB*TRI)           // 32040 unique edge rows
#define M_EDGE (BB*NN*NN)

// Scratch
__device__ __half g_p [(size_t)M_SYM * CC];    // 65 MB
__device__ __half g_h1[(size_t)M_SYM * CC];    // 65 MB
__device__ float  g_spart[(size_t)8 * M_SYM];  // s partials [8][M_SYM]
__device__ __half g_wt1[CC*CC];
__device__ __half g_wt2[HH*CC];
__device__ float g_at[BB*NN*CC];
__device__ float g_mt[BB*NN*CC];
__device__ float g_t1a[BB*NN*CC];
__device__ float g_t1m[BB*NN*CC];

// ---------------------------------------------------------------------------
__device__ __forceinline__ unsigned f2tf32(float x){
    unsigned r; asm("cvt.rna.tf32.f32 %0, %1;" : "=r"(r) : "f"(x)); return r;
}
__device__ __forceinline__ float4 round4(float4 v){
    return make_float4(__uint_as_float(f2tf32(v.x)), __uint_as_float(f2tf32(v.y)),
                       __uint_as_float(f2tf32(v.z)), __uint_as_float(f2tf32(v.w)));
}
__device__ __forceinline__ uint32_t smem_u32(const void* p){
    uint32_t a;
    asm("{ .reg .u64 t; cvta.to.shared.u64 t, %1; cvt.u32.u64 %0, t; }" : "=r"(a) : "l"(p));
    return a;
}
__device__ __forceinline__ void hmma(float c[4], const uint32_t a[4], const uint32_t b[2]){
    asm volatile("mma.sync.aligned.m16n8k16.row.col.f32.f16.f16.f32 "
        "{%0,%1,%2,%3}, {%4,%5,%6,%7}, {%8,%9}, {%0,%1,%2,%3};"
        : "+f"(c[0]), "+f"(c[1]), "+f"(c[2]), "+f"(c[3])
        : "r"(a[0]), "r"(a[1]), "r"(a[2]), "r"(a[3]), "r"(b[0]), "r"(b[1]));
}
__device__ __forceinline__ void ldmx4(uint32_t a[4], uint32_t addr){
    asm volatile("ldmatrix.sync.aligned.m8n8.x4.shared.b16 {%0,%1,%2,%3}, [%4];"
        : "=r"(a[0]), "=r"(a[1]), "=r"(a[2]), "=r"(a[3]) : "r"(addr));
}
__device__ __forceinline__ uint32_t pack_half2(float a, float b){
    __half2 h = __floats2half2_rn(a, b);
    return *reinterpret_cast<uint32_t*>(&h);
}
__device__ __forceinline__ void cp16(uint32_t dst, const void* src){
    asm volatile("cp.async.cg.shared.global [%0], [%1], 16;" :: "r"(dst), "l"(src));
}
__device__ __forceinline__ void cp_commit(){ asm volatile("cp.async.commit_group;"); }
template<int NW> __device__ __forceinline__ void cp_wait(){
    asm volatile("cp.async.wait_group %0;" :: "n"(NW));
}
// decode pair index p (0..TRI-1) -> (j <= i)
__device__ __forceinline__ void tri_decode(int p, int& j, int& i){
    i = (int)((sqrtf(8.0f*p + 1.0f) - 1.0f) * 0.5f);
    while ((i+1)*(i+2)/2 <= p) i++;
    while (i*(i+1)/2 > p) i--;
    j = p - i*(i+1)/2;
}

// ---------------------------------------------------------------------------
// p[row,:] = half( x[b,j,:] * x[b,i,:] ) over unique pairs (j<=i)
// ---------------------------------------------------------------------------
__global__ void __launch_bounds__(256) prod_kernel(const float* __restrict__ x, __half* __restrict__ p){
    const int row = blockIdx.x, seg = threadIdx.x;
    int b = row / TRI, pr = row - b*TRI;
    int j, i; tri_decode(pr, j, i);
    const float4 vj = ((const float4*)(x + (size_t)(b*NN + j)*CC))[seg];
    const float4 vi = ((const float4*)(x + (size_t)(b*NN + i)*CC))[seg];
    uint2 pk = make_uint2(pack_half2(vj.x*vi.x, vj.y*vi.y),
                          pack_half2(vj.z*vi.z, vj.w*vi.w));
    ((uint2*)p)[(size_t)row * 256 + seg] = pk;
}

// ---------------------------------------------------------------------------
// Wt[n,k] = half( W[k,n] )
// ---------------------------------------------------------------------------
__global__ void transpose_half(const float* __restrict__ W, __half* __restrict__ Wt, int K, int N){
    __shared__ float tile[32][33];
    int k0 = blockIdx.x*32, n0 = blockIdx.y*32;
    int tx = threadIdx.x, ty = threadIdx.y;
    #pragma unroll
    for (int r = 0; r < 32; r += 8)
        tile[ty + r][tx] = W[(size_t)(k0 + ty + r)*N + n0 + tx];
    __syncthreads();
    #pragma unroll
    for (int r = 0; r < 32; r += 8)
        Wt[(size_t)(n0 + ty + r)*K + k0 + tx] = __float2half(tile[tx][ty + r]);
}

// ---------------------------------------------------------------------------
// FP16 HMMA GEMM (R7 best config): CTA 128x256, BK=32, 3-stage cp.async,
// 8 warps (2x4), warp tile 64x64.
//   MODE 1: C half = relu(acc+bias)
//   MODE 2: no C; spart[col][r] = dot(relu(acc+bias), wvec)
// ---------------------------------------------------------------------------
#define LDH 40
#define BK 32
#define A_STAGE (128*LDH)   // halfs
#define B_STAGE (256*LDH)   // halfs

template<int MODE>
__global__ void __launch_bounds__(256, 1) hgemm(
    const __half* __restrict__ A, const __half* __restrict__ Bt,
    const float* __restrict__ bias, void* __restrict__ Cout,
    const float* __restrict__ wvec, float* __restrict__ spart,
    int M, int K, int N)
{
    extern __shared__ __half sh[];
    __half* Abase = sh;
    __half* Bbase = sh + 3*A_STAGE;

    const int t = threadIdx.x, warp = t >> 5, lane = t & 31;
    const int g = lane >> 2, tig = lane & 3;
    const int wm = (warp >> 2) * 64, wn = (warp & 3) * 64;
    const int mBase = blockIdx.y * 128, nBase = blockIdx.x * 256;

    const int aRow = t >> 1, aK = (t & 1) * 16;
    int garow = mBase + aRow; if (garow >= M) garow = M - 1;   // clamp
    const __half* agp = A + (size_t)garow * K + aK;
    const uint32_t aDst0 = smem_u32(Abase) + (uint32_t)((aRow*LDH + aK) * 2);
    const __half* bgp = Bt + (size_t)(nBase + t) * K;
    const uint32_t bDst0 = smem_u32(Bbase) + (uint32_t)(t * LDH * 2);

    const uint32_t uA = smem_u32(Abase);
    const uint32_t uB = smem_u32(Bbase);
    const int laneR = lane & 15, laneK = (lane >> 4) << 3;
    const int bg4 = lane >> 3, br = lane & 7;

    auto issue = [&](int kt){
        const int s = kt % 3;
        const int k0 = kt * BK;
        uint32_t da = aDst0 + (uint32_t)(s * A_STAGE * 2);
        cp16(da,      agp + k0);
        cp16(da + 16, agp + k0 + 8);
        uint32_t db = bDst0 + (uint32_t)(s * B_STAGE * 2);
        #pragma unroll
        for (int q = 0; q < 4; q++)
            cp16(db + q*16, bgp + k0 + q*8);
    };

    float acc[4][8][4];
    #pragma unroll
    for (int mi = 0; mi < 4; mi++)
        #pragma unroll
        for (int ni = 0; ni < 8; ni++)
            #pragma unroll
            for (int q = 0; q < 4; q++) acc[mi][ni][q] = 0.f;

    const int KT = K / BK;
    issue(0); cp_commit();
    issue(1); cp_commit();

    for (int kt = 0; kt < KT; kt++){
        cp_wait<1>();
        __syncthreads();
        if (kt + 2 < KT) issue(kt + 2);
        cp_commit();

        const int s = kt % 3;
        const uint32_t uAs = uA + (uint32_t)(s * A_STAGE * 2);
        const uint32_t uBs = uB + (uint32_t)(s * B_STAGE * 2);

        #pragma unroll
        for (int ko = 0; ko < BK; ko += 16){
            uint32_t af[4][4], bf[8][2];
            #pragma unroll
            for (int mi = 0; mi < 4; mi++)
                ldmx4(af[mi], uAs + (uint32_t)(((wm + mi*16 + laneR)*LDH + ko + laneK) * 2));
            #pragma unroll
            for (int nq = 0; nq < 4; nq++){
                uint32_t r4[4];
                int n = wn + nq*16 + (bg4 >> 1)*8 + br;
                int k = ko + (bg4 & 1)*8;
                ldmx4(r4, uBs + (uint32_t)((n*LDH + k) * 2));
                bf[nq*2  ][0] = r4[0]; bf[nq*2  ][1] = r4[1];
                bf[nq*2+1][0] = r4[2]; bf[nq*2+1][1] = r4[3];
            }
            #pragma unroll
            for (int mi = 0; mi < 4; mi++)
                #pragma unroll
                for (int ni = 0; ni < 8; ni++)
                    hmma(acc[mi][ni], af[mi], bf[ni]);
        }
    }

    if (MODE == 1){
        #pragma unroll
        for (int mi = 0; mi < 4; mi++)
            #pragma unroll
            for (int ni = 0; ni < 8; ni++){
                const int cb = nBase + wn + ni*8 + 2*tig;
                const float2 bs = *(const float2*)(bias + cb);
                #pragma unroll
                for (int hh = 0; hh < 2; hh++){
                    const int r = mBase + wm + mi*16 + g + hh*8;
                    if (r >= M) continue;
                    float z0 = fmaxf(acc[mi][ni][hh*2+0] + bs.x, 0.f);
                    float z1 = fmaxf(acc[mi][ni][hh*2+1] + bs.y, 0.f);
                    *(uint32_t*)((__half*)Cout + (size_t)r * N + cb) = pack_half2(z0, z1);
                }
            }
    } else {
        float rs[4][2];
        #pragma unroll
        for (int mi = 0; mi < 4; mi++){ rs[mi][0] = 0.f; rs[mi][1] = 0.f; }
        #pragma unroll
        for (int mi = 0; mi < 4; mi++)
            #pragma unroll
            for (int ni = 0; ni < 8; ni++){
                const int cb = nBase + wn + ni*8 + 2*tig;
                const float2 bs = *(const float2*)(bias + cb);
                const float2 wv = *(const float2*)(wvec + cb);
                #pragma unroll
                for (int hh = 0; hh < 2; hh++){
                    float z0 = fmaxf(acc[mi][ni][hh*2+0] + bs.x, 0.f);
                    float z1 = fmaxf(acc[mi][ni][hh*2+1] + bs.y, 0.f);
                    rs[mi][hh] += z0*wv.x + z1*wv.y;
                }
            }
        const int col = blockIdx.x * 4 + (warp & 3);
        #pragma unroll
        for (int mi = 0; mi < 4; mi++)
            #pragma unroll
            for (int hh = 0; hh < 2; hh++){
                float v = rs[mi][hh];
                v += __shfl_xor_sync(0xffffffffu, v, 1);
                v += __shfl_xor_sync(0xffffffffu, v, 2);
                const int r = mBase + wm + mi*16 + g + hh*8;
                if (tig == 0 && r < M)
                    spart[(size_t)col * M_SYM + r] = v;
            }
    }
}

// ---------------------------------------------------------------------------
// legacy tf32 GEMM for small 712-row GEMMs; blockIdx.z merges the layer-1 pair
// ---------------------------------------------------------------------------
__device__ __forceinline__ void mma_frag(float c[4], const unsigned a[4], const unsigned b[2]){
    asm volatile("mma.sync.aligned.m16n8k8.row.col.f32.tf32.tf32.f32 "
        "{%0,%1,%2,%3}, {%4,%5,%6,%7}, {%8,%9}, {%0,%1,%2,%3};\n"
        : "+f"(c[0]), "+f"(c[1]), "+f"(c[2]), "+f"(c[3])
        : "r"(a[0]), "r"(a[1]), "r"(a[2]), "r"(a[3]), "r"(b[0]), "r"(b[1]));
}
__global__ void __launch_bounds__(256) mma_gemm(
    const float* __restrict__ A0, const float* __restrict__ A1,
    const float* __restrict__ B0, const float* __restrict__ B1,
    const float* __restrict__ bias0, const float* __restrict__ bias1,
    float* __restrict__ C0, float* __restrict__ C1,
    const float* __restrict__ aux, int M, int K, int Ncols, int mode)
{
    const float* A    = blockIdx.z ? A1 : A0;
    const float* Bm   = blockIdx.z ? B1 : B0;
    const float* bias = blockIdx.z ? bias1 : bias0;
    float* Cmat       = blockIdx.z ? C1 : C0;

    __shared__ __align__(16) float As[2][16][136];
    __shared__ __align__(16) float Bs[2][16][136];
    const int t = threadIdx.x, warp = t >> 5, lane = t & 31;
    const int g = lane >> 2, tig = lane & 3;
    const int wm = (warp >> 2) * 64, wn = (warp & 3) * 32;
    const int mBase = blockIdx.y * 128, nBase = blockIdx.x * 128;
    const int arow = t >> 2, akq = (t & 3) * 4;
    const int grow0 = mBase + arow, grow1 = grow0 + 64;
    const bool v0 = grow0 < M, v1 = grow1 < M;
    const float* ap0 = v0 ? A + (size_t)grow0 * K : nullptr;
    const float* ap1 = v1 ? A + (size_t)grow1 * K : nullptr;
    const int bkr = t >> 5, bnc = (t & 31) * 4;
    float4 a0s, a1s, b0s, b1s;
    auto load_g = [&](int k0){
        const float4 z = make_float4(0,0,0,0);
        a0s = v0 ? *(const float4*)(ap0 + k0 + akq) : z;
        a1s = v1 ? *(const float4*)(ap1 + k0 + akq) : z;
        b0s = *(const float4*)(Bm + (size_t)(k0 + bkr    ) * Ncols + nBase + bnc);
        b1s = *(const float4*)(Bm + (size_t)(k0 + bkr + 8) * Ncols + nBase + bnc);
    };
    auto store_s = [&](int buf){
        float4 c0 = round4(a0s), c1 = round4(a1s);
        As[buf][akq+0][arow] = c0.x; As[buf][akq+1][arow] = c0.y;
        As[buf][akq+2][arow] = c0.z; As[buf][akq+3][arow] = c0.w;
        As[buf][akq+0][arow+64] = c1.x; As[buf][akq+1][arow+64] = c1.y;
        As[buf][akq+2][arow+64] = c1.z; As[buf][akq+3][arow+64] = c1.w;
        *(float4*)&Bs[buf][bkr][bnc]     = round4(b0s);
        *(float4*)&Bs[buf][bkr + 8][bnc] = round4(b1s);
    };
    float acc[4][4][4];
    #pragma unroll
    for (int mi = 0; mi < 4; mi++)
        #pragma unroll
        for (int ni = 0; ni < 4; ni++)
            #pragma unroll
            for (int q = 0; q < 4; q++) acc[mi][ni][q] = 0.f;
    load_g(0); store_s(0); __syncthreads();
    const int KT = K / 16;
    for (int kt = 0; kt < KT; kt++){
        const int cur = kt & 1;
        if (kt + 1 < KT) load_g((kt + 1) * 16);
        #pragma unroll
        for (int ko = 0; ko < 16; ko += 8){
            unsigned af[4][4], bf[4][2];
            #pragma unroll
            for (int mi = 0; mi < 4; mi++){
                const int m0 = wm + mi*16 + g;
                af[mi][0] = __float_as_uint(As[cur][ko + tig    ][m0    ]);
                af[mi][1] = __float_as_uint(As[cur][ko + tig    ][m0 + 8]);
                af[mi][2] = __float_as_uint(As[cur][ko + tig + 4][m0    ]);
                af[mi][3] = __float_as_uint(As[cur][ko + tig + 4][m0 + 8]);
            }
            #pragma unroll
            for (int ni = 0; ni < 4; ni++){
                const int n0 = wn + ni*8 + g;
                bf[ni][0] = __float_as_uint(Bs[cur][ko + tig    ][n0]);
                bf[ni][1] = __float_as_uint(Bs[cur][ko + tig + 4][n0]);
            }
            #pragma unroll
            for (int mi = 0; mi < 4; mi++)
                #pragma unroll
                for (int ni = 0; ni < 4; ni++)
                    mma_frag(acc[mi][ni], af[mi], bf[ni]);
        }
        if (kt + 1 < KT) store_s((kt + 1) & 1);
        __syncthreads();
    }
    #pragma unroll
    for (int mi = 0; mi < 4; mi++)
        #pragma unroll
        for (int ni = 0; ni < 4; ni++){
            const int cb = nBase + wn + ni*8 + 2*tig;
            const float2 bs = *(const float2*)(bias + cb);
            #pragma unroll
            for (int hh = 0; hh < 2; hh++){
                const int r = mBase + wm + mi*16 + g + hh*8;
                if (r >= M) continue;
                float z0 = acc[mi][ni][hh*2+0] + bs.x;
                float z1 = acc[mi][ni][hh*2+1] + bs.y;
                if (mode == 0){ z0 = fmaxf(z0, 0.f); z1 = fmaxf(z1, 0.f); }
                else {
                    const float2 a = *(const float2*)(aux + (size_t)r * Ncols + cb);
                    z0 += a.x; z1 += a.y;
                    if (mode == 2){ z0 *= (1.f/3.f); z1 *= (1.f/3.f); }
                }
                *(float2*)(Cmat + (size_t)r * Ncols + cb) = make_float2(z0, z1);
            }
        }
}

// ---------------------------------------------------------------------------
// aggregation with fused s finalize (triangular s lookup)
// ---------------------------------------------------------------------------
__global__ void __launch_bounds__(256) agg_kernel(
    const float* __restrict__ x, const float* __restrict__ spart,
    const float* __restrict__ ba3,
    const float* __restrict__ adj_add, const float* __restrict__ adj_mod,
    float* __restrict__ at, float* __restrict__ mt)
{
    __shared__ float sv_sh[NN];
    int bi = blockIdx.x;
    int b = bi / NN, i = bi - b*NN;
    if (threadIdx.x < NN){
        int j = threadIdx.x;
        int lo = j <= i ? j : i;
        int hi = j <= i ? i : j;
        int row = b*TRI + hi*(hi+1)/2 + lo;
        float v = ba3[0];
        #pragma unroll
        for (int c = 0; c < 8; c++) v += spart[(size_t)c * M_SYM + row];
        sv_sh[j] = 1.f / (1.f + expf(-v));
    }
    __syncthreads();

    int f = threadIdx.x * 4;
    float4 aa = make_float4(0,0,0,0), mm = make_float4(0,0,0,0);
    for (int j = 0; j < NN; j++){
        float wa = sv_sh[j] * adj_add[j*NN + i];
        float wm = adj_mod[j*NN + i];
        float4 xv = *(const float4*)(x + (size_t)(b*NN + j)*CC + f);
        aa.x = fmaf(wa, xv.x, aa.x); aa.y = fmaf(wa, xv.y, aa.y);
        aa.z = fmaf(wa, xv.z, aa.z); aa.w = fmaf(wa, xv.w, aa.w);
        mm.x = fmaf(wm, xv.x, mm.x); mm.y = fmaf(wm, xv.y, mm.y);
        mm.z = fmaf(wm, xv.z, mm.z); mm.w = fmaf(wm, xv.w, mm.w);
    }
    float4 xv = *(const float4*)(x + (size_t)bi * CC + f);
    mm.x *= xv.x; mm.y *= xv.y; mm.z *= xv.z; mm.w *= xv.w;
    *(float4*)(at + (size_t)bi * CC + f) = aa;
    *(float4*)(mt + (size_t)bi * CC + f) = mm;
}

// ---------------------------------------------------------------------------
extern "C" void kernel_launch(void* const* d_in, const int* in_sizes, int n_in,
                              void* d_out, int out_size)
{
    const float* x    = (const float*)d_in[0];
    const float* Wa1  = (const float*)d_in[3];
    const float* ba1  = (const float*)d_in[4];
    const float* Wa2  = (const float*)d_in[5];
    const float* ba2  = (const float*)d_in[6];
    const float* Wa3  = (const float*)d_in[7];
    const float* ba3  = (const float*)d_in[8];
    float* out = (float*)d_out;

    __half *p, *h1, *wt1, *wt2;
    float *spart, *at, *mt, *t1a, *t1m;
    cudaGetSymbolAddress((void**)&p,    g_p);
    cudaGetSymbolAddress((void**)&h1,   g_h1);
    cudaGetSymbolAddress((void**)&spart,g_spart);
    cudaGetSymbolAddress((void**)&wt1,  g_wt1);
    cudaGetSymbolAddress((void**)&wt2,  g_wt2);
    cudaGetSymbolAddress((void**)&at,   g_at);
    cudaGetSymbolAddress((void**)&mt,   g_mt);
    cudaGetSymbolAddress((void**)&t1a,  g_t1a);
    cudaGetSymbolAddress((void**)&t1m,  g_t1m);

    const int M = M_SYM, MR = BB * NN;
    const int MT = (M + 127) / 128;   // 251
    const int SMEM = 3 * (A_STAGE + B_STAGE) * 2;   // 92160 B

    cudaFuncSetAttribute(hgemm<1>, cudaFuncAttributeMaxDynamicSharedMemorySize, SMEM);
    cudaFuncSetAttribute(hgemm<2>, cudaFuncAttributeMaxDynamicSharedMemorySize, SMEM);

    // prep
    transpose_half<<<dim3(CC/32, CC/32), dim3(32,8)>>>(Wa1, wt1, CC, CC);
    transpose_half<<<dim3(CC/32, HH/32), dim3(32,8)>>>(Wa2, wt2, CC, HH);
    prod_kernel<<<M, 256>>>(x, p);

    // h1 = relu(p @ Wa1 + ba1)   [half out]  — unique pairs only
    hgemm<1><<<dim3(CC/256, MT), 256, SMEM>>>(p, wt1, ba1, h1, nullptr, nullptr, M, CC, CC);
    // s partials (h2 never materialized)
    hgemm<2><<<dim3(HH/256, MT), 256, SMEM>>>(h1, wt2, ba2, nullptr, Wa3, spart, M, CC, HH);

    agg_kernel<<<MR, 256>>>(x, spart, ba3, (const float*)d_in[1], (const float*)d_in[2], at, mt);

    const int MRT = (MR + 127) / 128; // 6
    mma_gemm<<<dim3(CC/128, MRT, 2), 256>>>(
        at, mt, (const float*)d_in[9], (const float*)d_in[13],
        (const float*)d_in[10], (const float*)d_in[14],
        t1a, t1m, nullptr, MR, CC, CC, 0);
    mma_gemm<<<dim3(CC/128, MRT, 1), 256>>>(
        t1a, nullptr, (const float*)d_in[11], nullptr,
        (const float*)d_in[12], nullptr,
        out, nullptr, x, MR, CC, CC, 1);
    mma_gemm<<<dim3(CC/128, MRT, 1), 256>>>(
        t1m, nullptr, (const float*)d_in[15], nullptr,
        (const float*)d_in[16], nullptr,
        out, nullptr, out, MR, CC, CC, 2);
}

// round 11
// speedup vs baseline: 2.4702x; 1.3937x over previous
#include <cuda_runtime.h>
#include <cuda.h>
#include <cuda_fp16.h>
#include <cstdint>
#include <math.h>

#define BB 8
#define NN 89
#define CC 1024
#define HH 512
#define TRI (NN*(NN+1)/2)        // 4005 pairs (j<=i)
#define M_SYM (BB*TRI)           // 32040 unique edge rows

// Scratch
__device__ __half g_p [(size_t)M_SYM * CC];
__device__ __half g_h1[(size_t)M_SYM * CC];
__device__ float  g_spart[(size_t)8 * M_SYM];
__device__ __half g_wt1[CC*CC];
__device__ __half g_wt2[HH*CC];
__device__ float g_at[BB*NN*CC];
__device__ float g_mt[BB*NN*CC];
__device__ float g_t1a[BB*NN*CC];
__device__ float g_t1m[BB*NN*CC];

// ---------------------------------------------------------------------------
__device__ __forceinline__ unsigned f2tf32(float x){
    unsigned r; asm("cvt.rna.tf32.f32 %0, %1;" : "=r"(r) : "f"(x)); return r;
}
__device__ __forceinline__ float4 round4(float4 v){
    return make_float4(__uint_as_float(f2tf32(v.x)), __uint_as_float(f2tf32(v.y)),
                       __uint_as_float(f2tf32(v.z)), __uint_as_float(f2tf32(v.w)));
}
__device__ __forceinline__ uint32_t smem_u32(const void* p){
    uint32_t a;
    asm("{ .reg .u64 t; cvta.to.shared.u64 t, %1; cvt.u32.u64 %0, t; }" : "=r"(a) : "l"(p));
    return a;
}
__device__ __forceinline__ void hmma(float c[4], const uint32_t a[4], const uint32_t b[2]){
    asm volatile("mma.sync.aligned.m16n8k16.row.col.f32.f16.f16.f32 "
        "{%0,%1,%2,%3}, {%4,%5,%6,%7}, {%8,%9}, {%0,%1,%2,%3};"
        : "+f"(c[0]), "+f"(c[1]), "+f"(c[2]), "+f"(c[3])
        : "r"(a[0]), "r"(a[1]), "r"(a[2]), "r"(a[3]), "r"(b[0]), "r"(b[1]));
}
__device__ __forceinline__ void ldmx4(uint32_t a[4], uint32_t addr){
    asm volatile("ldmatrix.sync.aligned.m8n8.x4.shared.b16 {%0,%1,%2,%3}, [%4];"
        : "=r"(a[0]), "=r"(a[1]), "=r"(a[2]), "=r"(a[3]) : "r"(addr));
}
__device__ __forceinline__ uint32_t pack_half2(float a, float b){
    __half2 h = __floats2half2_rn(a, b);
    return *reinterpret_cast<uint32_t*>(&h);
}
__device__ __forceinline__ uint32_t sw128(uint32_t b){ return b ^ ((b >> 3) & 0x70u); }

__device__ __forceinline__ void mbar_init(uint32_t a, uint32_t c){
    asm volatile("mbarrier.init.shared.b64 [%0], %1;" :: "r"(a), "r"(c) : "memory");
}
__device__ __forceinline__ void mbar_expect(uint32_t a, uint32_t bytes){
    asm volatile("mbarrier.arrive.expect_tx.shared.b64 _, [%0], %1;" :: "r"(a), "r"(bytes) : "memory");
}
__device__ __forceinline__ void mbar_wait(uint32_t a, uint32_t par){
    asm volatile("{\n\t.reg .pred P;\n"
        "LW_%=:\n\t"
        "mbarrier.try_wait.parity.acquire.cta.shared::cta.b64 P, [%0], %1, 0x989680;\n\t"
        "@!P bra LW_%=;\n\t}" :: "r"(a), "r"(par) : "memory");
}
__device__ __forceinline__ void tma2d(uint32_t dst, const CUtensorMap* m, int cx, int cy, uint32_t mb){
    asm volatile("cp.async.bulk.tensor.2d.shared::cta.global.tile.mbarrier::complete_tx::bytes "
                 "[%0], [%1, {%2, %3}], [%4];"
                 :: "r"(dst), "l"(m), "r"(cx), "r"(cy), "r"(mb) : "memory");
}
// decode pair index p (0..TRI-1) -> (j <= i)
__device__ __forceinline__ void tri_decode(int p, int& j, int& i){
    i = (int)((sqrtf(8.0f*p + 1.0f) - 1.0f) * 0.5f);
    while ((i+1)*(i+2)/2 <= p) i++;
    while (i*(i+1)/2 > p) i--;
    j = p - i*(i+1)/2;
}

// ---------------------------------------------------------------------------
__global__ void __launch_bounds__(256) prod_kernel(const float* __restrict__ x, __half* __restrict__ p){
    const int row = blockIdx.x, seg = threadIdx.x;
    int b = row / TRI, pr = row - b*TRI;
    int j, i; tri_decode(pr, j, i);
    const float4 vj = ((const float4*)(x + (size_t)(b*NN + j)*CC))[seg];
    const float4 vi = ((const float4*)(x + (size_t)(b*NN + i)*CC))[seg];
    uint2 pk = make_uint2(pack_half2(vj.x*vi.x, vj.y*vi.y),
                          pack_half2(vj.z*vi.z, vj.w*vi.w));
    ((uint2*)p)[(size_t)row * 256 + seg] = pk;
}

__global__ void transpose_half(const float* __restrict__ W, __half* __restrict__ Wt, int K, int N){
    __shared__ float tile[32][33];
    int k0 = blockIdx.x*32, n0 = blockIdx.y*32;
    int tx = threadIdx.x, ty = threadIdx.y;
    #pragma unroll
    for (int r = 0; r < 32; r += 8)
        tile[ty + r][tx] = W[(size_t)(k0 + ty + r)*N + n0 + tx];
    __syncthreads();
    #pragma unroll
    for (int r = 0; r < 32; r += 8)
        Wt[(size_t)(n0 + ty + r)*K + k0 + tx] = __float2half(tile[tx][ty + r]);
}

// ---------------------------------------------------------------------------
// FP16 HMMA GEMM v5: CTA 128x256, BK=64 (128B swizzled rows), TMA staging,
// 3-stage mbarrier pipeline, 8 warps (2x4), warp tile 64x64.
//   MODE 1: C half = relu(acc+bias)
//   MODE 2: spart[col][r] = dot(relu(acc+bias), wvec)
// ---------------------------------------------------------------------------
#define BK 64
#define A_ST_B 16384            // bytes: 128 rows x 128B
#define B_ST_B 32768            // bytes: 256 rows x 128B
#define STAGE_B (A_ST_B + B_ST_B)

template<int MODE>
__global__ void __launch_bounds__(256, 1) hgemm(
    const __grid_constant__ CUtensorMap mapA,
    const __grid_constant__ CUtensorMap mapB,
    const float* __restrict__ bias, void* __restrict__ Cout,
    const float* __restrict__ wvec, float* __restrict__ spart,
    int M, int K, int N)
{
    extern __shared__ __align__(1024) char sh[];
    __shared__ __align__(8) unsigned long long mbar[3];

    const int t = threadIdx.x, warp = t >> 5, lane = t & 31;
    const int g = lane >> 2, tig = lane & 3;
    const int wm = (warp >> 2) * 64, wn = (warp & 3) * 64;
    const int mBase = blockIdx.y * 128, nBase = blockIdx.x * 256;

    const uint32_t uS = smem_u32(sh);
    const uint32_t uMB = smem_u32(&mbar[0]);
    const int laneR = lane & 15, laneK = (lane >> 4) << 3;
    const int bg4 = lane >> 3, br = lane & 7;

    if (t == 0){
        #pragma unroll
        for (int s = 0; s < 3; s++) mbar_init(uMB + s*8, 1);
        asm volatile("fence.proxy.async.shared::cta;" ::: "memory");
    }
    __syncthreads();

    const int KT = K / BK;   // 16
    if (t == 0){
        #pragma unroll
        for (int s = 0; s < 2; s++){
            mbar_expect(uMB + s*8, STAGE_B);
            tma2d(uS + s*STAGE_B,          &mapA, s*BK, mBase, uMB + s*8);
            tma2d(uS + s*STAGE_B + A_ST_B, &mapB, s*BK, nBase, uMB + s*8);
        }
    }

    float acc[4][8][4];
    #pragma unroll
    for (int mi = 0; mi < 4; mi++)
        #pragma unroll
        for (int ni = 0; ni < 8; ni++)
            #pragma unroll
            for (int q = 0; q < 4; q++) acc[mi][ni][q] = 0.f;

    int ph[3] = {0, 0, 0};
    for (int kt = 0; kt < KT; kt++){
        const int b = kt % 3;
        mbar_wait(uMB + b*8, ph[b]); ph[b] ^= 1;

        const uint32_t uA = uS + (uint32_t)(b * STAGE_B);
        const uint32_t uB = uA + A_ST_B;

        #pragma unroll
        for (int ko = 0; ko < BK; ko += 16){
            uint32_t af[4][4], bf[8][2];
            #pragma unroll
            for (int mi = 0; mi < 4; mi++){
                uint32_t byte = (uint32_t)((wm + mi*16 + laneR)*128 + (ko + laneK)*2);
                ldmx4(af[mi], uA + sw128(byte));
            }
            #pragma unroll
            for (int nq = 0; nq < 4; nq++){
                uint32_t r4[4];
                int n = wn + nq*16 + (bg4 >> 1)*8 + br;
                int k = ko + (bg4 & 1)*8;
                uint32_t byte = (uint32_t)(n*128 + k*2);
                ldmx4(r4, uB + sw128(byte));
                bf[nq*2  ][0] = r4[0]; bf[nq*2  ][1] = r4[1];
                bf[nq*2+1][0] = r4[2]; bf[nq*2+1][1] = r4[3];
            }
            #pragma unroll
            for (int mi = 0; mi < 4; mi++)
                #pragma unroll
                for (int ni = 0; ni < 8; ni++)
                    hmma(acc[mi][ni], af[mi], bf[ni]);
        }

        __syncthreads();            // all warps done reading buffer (kt-1)%3
        if (t == 0 && kt + 2 < KT){
            const int bp = (kt + 2) % 3;
            mbar_expect(uMB + bp*8, STAGE_B);
            tma2d(uS + bp*STAGE_B,          &mapA, (kt+2)*BK, mBase, uMB + bp*8);
            tma2d(uS + bp*STAGE_B + A_ST_B, &mapB, (kt+2)*BK, nBase, uMB + bp*8);
        }
    }

    if (MODE == 1){
        #pragma unroll
        for (int mi = 0; mi < 4; mi++)
            #pragma unroll
            for (int ni = 0; ni < 8; ni++){
                const int cb = nBase + wn + ni*8 + 2*tig;
                const float2 bs = *(const float2*)(bias + cb);
                #pragma unroll
                for (int hh = 0; hh < 2; hh++){
                    const int r = mBase + wm + mi*16 + g + hh*8;
                    if (r >= M) continue;
                    float z0 = fmaxf(acc[mi][ni][hh*2+0] + bs.x, 0.f);
                    float z1 = fmaxf(acc[mi][ni][hh*2+1] + bs.y, 0.f);
                    *(uint32_t*)((__half*)Cout + (size_t)r * N + cb) = pack_half2(z0, z1);
                }
            }
    } else {
        float rs[4][2];
        #pragma unroll
        for (int mi = 0; mi < 4; mi++){ rs[mi][0] = 0.f; rs[mi][1] = 0.f; }
        #pragma unroll
        for (int mi = 0; mi < 4; mi++)
            #pragma unroll
            for (int ni = 0; ni < 8; ni++){
                const int cb = nBase + wn + ni*8 + 2*tig;
                const float2 bs = *(const float2*)(bias + cb);
                const float2 wv = *(const float2*)(wvec + cb);
                #pragma unroll
                for (int hh = 0; hh < 2; hh++){
                    float z0 = fmaxf(acc[mi][ni][hh*2+0] + bs.x, 0.f);
                    float z1 = fmaxf(acc[mi][ni][hh*2+1] + bs.y, 0.f);
                    rs[mi][hh] += z0*wv.x + z1*wv.y;
                }
            }
        const int col = blockIdx.x * 4 + (warp & 3);
        #pragma unroll
        for (int mi = 0; mi < 4; mi++)
            #pragma unroll
            for (int hh = 0; hh < 2; hh++){
                float v = rs[mi][hh];
                v += __shfl_xor_sync(0xffffffffu, v, 1);
                v += __shfl_xor_sync(0xffffffffu, v, 2);
                const int r = mBase + wm + mi*16 + g + hh*8;
                if (tig == 0 && r < M)
                    spart[(size_t)col * M_SYM + r] = v;
            }
    }
}

// ---------------------------------------------------------------------------
// legacy tf32 GEMM for small 712-row GEMMs; blockIdx.z merges the layer-1 pair
// ---------------------------------------------------------------------------
__device__ __forceinline__ void mma_frag(float c[4], const unsigned a[4], const unsigned b[2]){
    asm volatile("mma.sync.aligned.m16n8k8.row.col.f32.tf32.tf32.f32 "
        "{%0,%1,%2,%3}, {%4,%5,%6,%7}, {%8,%9}, {%0,%1,%2,%3};\n"
        : "+f"(c[0]), "+f"(c[1]), "+f"(c[2]), "+f"(c[3])
        : "r"(a[0]), "r"(a[1]), "r"(a[2]), "r"(a[3]), "r"(b[0]), "r"(b[1]));
}
__global__ void __launch_bounds__(256) mma_gemm(
    const float* __restrict__ A0, const float* __restrict__ A1,
    const float* __restrict__ B0, const float* __restrict__ B1,
    const float* __restrict__ bias0, const float* __restrict__ bias1,
    float* __restrict__ C0, float* __restrict__ C1,
    const float* __restrict__ aux, int M, int K, int Ncols, int mode)
{
    const float* A    = blockIdx.z ? A1 : A0;
    const float* Bm   = blockIdx.z ? B1 : B0;
    const float* bias = blockIdx.z ? bias1 : bias0;
    float* Cmat       = blockIdx.z ? C1 : C0;

    __shared__ __align__(16) float As[2][16][136];
    __shared__ __align__(16) float Bs[2][16][136];
    const int t = threadIdx.x, warp = t >> 5, lane = t & 31;
    const int g = lane >> 2, tig = lane & 3;
    const int wm = (warp >> 2) * 64, wn = (warp & 3) * 32;
    const int mBase = blockIdx.y * 128, nBase = blockIdx.x * 128;
    const int arow = t >> 2, akq = (t & 3) * 4;
    const int grow0 = mBase + arow, grow1 = grow0 + 64;
    const bool v0 = grow0 < M, v1 = grow1 < M;
    const float* ap0 = v0 ? A + (size_t)grow0 * K : nullptr;
    const float* ap1 = v1 ? A + (size_t)grow1 * K : nullptr;
    const int bkr = t >> 5, bnc = (t & 31) * 4;
    float4 a0s, a1s, b0s, b1s;
    auto load_g = [&](int k0){
        const float4 z = make_float4(0,0,0,0);
        a0s = v0 ? *(const float4*)(ap0 + k0 + akq) : z;
        a1s = v1 ? *(const float4*)(ap1 + k0 + akq) : z;
        b0s = *(const float4*)(Bm + (size_t)(k0 + bkr    ) * Ncols + nBase + bnc);
        b1s = *(const float4*)(Bm + (size_t)(k0 + bkr + 8) * Ncols + nBase + bnc);
    };
    auto store_s = [&](int buf){
        float4 c0 = round4(a0s), c1 = round4(a1s);
        As[buf][akq+0][arow] = c0.x; As[buf][akq+1][arow] = c0.y;
        As[buf][akq+2][arow] = c0.z; As[buf][akq+3][arow] = c0.w;
        As[buf][akq+0][arow+64] = c1.x; As[buf][akq+1][arow+64] = c1.y;
        As[buf][akq+2][arow+64] = c1.z; As[buf][akq+3][arow+64] = c1.w;
        *(float4*)&Bs[buf][bkr][bnc]     = round4(b0s);
        *(float4*)&Bs[buf][bkr + 8][bnc] = round4(b1s);
    };
    float acc[4][4][4];
    #pragma unroll
    for (int mi = 0; mi < 4; mi++)
        #pragma unroll
        for (int ni = 0; ni < 4; ni++)
            #pragma unroll
            for (int q = 0; q < 4; q++) acc[mi][ni][q] = 0.f;
    load_g(0); store_s(0); __syncthreads();
    const int KT = K / 16;
    for (int kt = 0; kt < KT; kt++){
        const int cur = kt & 1;
        if (kt + 1 < KT) load_g((kt + 1) * 16);
        #pragma unroll
        for (int ko = 0; ko < 16; ko += 8){
            unsigned af[4][4], bf[4][2];
            #pragma unroll
            for (int mi = 0; mi < 4; mi++){
                const int m0 = wm + mi*16 + g;
                af[mi][0] = __float_as_uint(As[cur][ko + tig    ][m0    ]);
                af[mi][1] = __float_as_uint(As[cur][ko + tig    ][m0 + 8]);
                af[mi][2] = __float_as_uint(As[cur][ko + tig + 4][m0    ]);
                af[mi][3] = __float_as_uint(As[cur][ko + tig + 4][m0 + 8]);
            }
            #pragma unroll
            for (int ni = 0; ni < 4; ni++){
                const int n0 = wn + ni*8 + g;
                bf[ni][0] = __float_as_uint(Bs[cur][ko + tig    ][n0]);
                bf[ni][1] = __float_as_uint(Bs[cur][ko + tig + 4][n0]);
            }
            #pragma unroll
            for (int mi = 0; mi < 4; mi++)
                #pragma unroll
                for (int ni = 0; ni < 4; ni++)
                    mma_frag(acc[mi][ni], af[mi], bf[ni]);
        }
        if (kt + 1 < KT) store_s((kt + 1) & 1);
        __syncthreads();
    }
    #pragma unroll
    for (int mi = 0; mi < 4; mi++)
        #pragma unroll
        for (int ni = 0; ni < 4; ni++){
            const int cb = nBase + wn + ni*8 + 2*tig;
            const float2 bs = *(const float2*)(bias + cb);
            #pragma unroll
            for (int hh = 0; hh < 2; hh++){
                const int r = mBase + wm + mi*16 + g + hh*8;
                if (r >= M) continue;
                float z0 = acc[mi][ni][hh*2+0] + bs.x;
                float z1 = acc[mi][ni][hh*2+1] + bs.y;
                if (mode == 0){ z0 = fmaxf(z0, 0.f); z1 = fmaxf(z1, 0.f); }
                else {
                    const float2 a = *(const float2*)(aux + (size_t)r * Ncols + cb);
                    z0 += a.x; z1 += a.y;
                    if (mode == 2){ z0 *= (1.f/3.f); z1 *= (1.f/3.f); }
                }
                *(float2*)(Cmat + (size_t)r * Ncols + cb) = make_float2(z0, z1);
            }
        }
}

// ---------------------------------------------------------------------------
// aggregation with fused s finalize (triangular s lookup)
// ---------------------------------------------------------------------------
__global__ void __launch_bounds__(256) agg_kernel(
    const float* __restrict__ x, const float* __restrict__ spart,
    const float* __restrict__ ba3,
    const float* __restrict__ adj_add, const float* __restrict__ adj_mod,
    float* __restrict__ at, float* __restrict__ mt)
{
    __shared__ float sv_sh[NN];
    int bi = blockIdx.x;
    int b = bi / NN, i = bi - b*NN;
    if (threadIdx.x < NN){
        int j = threadIdx.x;
        int lo = j <= i ? j : i;
        int hi = j <= i ? i : j;
        int row = b*TRI + hi*(hi+1)/2 + lo;
        float v = ba3[0];
        #pragma unroll
        for (int c = 0; c < 8; c++) v += spart[(size_t)c * M_SYM + row];
        sv_sh[j] = 1.f / (1.f + expf(-v));
    }
    __syncthreads();

    int f = threadIdx.x * 4;
    float4 aa = make_float4(0,0,0,0), mm = make_float4(0,0,0,0);
    for (int j = 0; j < NN; j++){
        float wa = sv_sh[j] * adj_add[j*NN + i];
        float wm = adj_mod[j*NN + i];
        float4 xv = *(const float4*)(x + (size_t)(b*NN + j)*CC + f);
        aa.x = fmaf(wa, xv.x, aa.x); aa.y = fmaf(wa, xv.y, aa.y);
        aa.z = fmaf(wa, xv.z, aa.z); aa.w = fmaf(wa, xv.w, aa.w);
        mm.x = fmaf(wm, xv.x, mm.x); mm.y = fmaf(wm, xv.y, mm.y);
        mm.z = fmaf(wm, xv.z, mm.z); mm.w = fmaf(wm, xv.w, mm.w);
    }
    float4 xv = *(const float4*)(x + (size_t)bi * CC + f);
    mm.x *= xv.x; mm.y *= xv.y; mm.z *= xv.z; mm.w *= xv.w;
    *(float4*)(at + (size_t)bi * CC + f) = aa;
    *(float4*)(mt + (size_t)bi * CC + f) = mm;
}

// ---------------------------------------------------------------------------
// host
// ---------------------------------------------------------------------------
typedef CUresult (*EncodeFn)(CUtensorMap*, CUtensorMapDataType, cuuint32_t, void*,
    const cuuint64_t*, const cuuint64_t*, const cuuint32_t*, const cuuint32_t*,
    CUtensorMapInterleave, CUtensorMapSwizzle, CUtensorMapL2promotion, CUtensorMapFloatOOBfill);

static EncodeFn get_encoder(){
    static EncodeFn fn = nullptr;
    if (!fn){
        cudaDriverEntryPointQueryResult qr;
#if CUDART_VERSION >= 12050
        cudaGetDriverEntryPointByVersion("cuTensorMapEncodeTiled", (void**)&fn, 12000,
                                         cudaEnableDefault, &qr);
#else
        cudaGetDriverEntryPoint("cuTensorMapEncodeTiled", (void**)&fn, cudaEnableDefault, &qr);
#endif
    }
    return fn;
}
static void make_map(CUtensorMap* m, void* ptr, uint64_t kdim, uint64_t rows, uint32_t boxRows){
    cuuint64_t dims[2] = {kdim, rows};
    cuuint64_t strides[1] = {kdim * 2};   // halfs
    cuuint32_t box[2] = {BK, boxRows};
    cuuint32_t es[2] = {1, 1};
    get_encoder()(m, CU_TENSOR_MAP_DATA_TYPE_FLOAT16, 2, ptr, dims, strides, box, es,
        CU_TENSOR_MAP_INTERLEAVE_NONE, CU_TENSOR_MAP_SWIZZLE_128B,
        CU_TENSOR_MAP_L2_PROMOTION_L2_128B, CU_TENSOR_MAP_FLOAT_OOB_FILL_NONE);
}

extern "C" void kernel_launch(void* const* d_in, const int* in_sizes, int n_in,
                              void* d_out, int out_size)
{
    const float* x    = (const float*)d_in[0];
    const float* Wa1  = (const float*)d_in[3];
    const float* ba1  = (const float*)d_in[4];
    const float* Wa2  = (const float*)d_in[5];
    const float* ba2  = (const float*)d_in[6];
    const float* Wa3  = (const float*)d_in[7];
    const float* ba3  = (const float*)d_in[8];
    float* out = (float*)d_out;

    __half *p, *h1, *wt1, *wt2;
    float *spart, *at, *mt, *t1a, *t1m;
    cudaGetSymbolAddress((void**)&p,    g_p);
    cudaGetSymbolAddress((void**)&h1,   g_h1);
    cudaGetSymbolAddress((void**)&spart,g_spart);
    cudaGetSymbolAddress((void**)&wt1,  g_wt1);
    cudaGetSymbolAddress((void**)&wt2,  g_wt2);
    cudaGetSymbolAddress((void**)&at,   g_at);
    cudaGetSymbolAddress((void**)&mt,   g_mt);
    cudaGetSymbolAddress((void**)&t1a,  g_t1a);
    cudaGetSymbolAddress((void**)&t1m,  g_t1m);

    const int M = M_SYM, MR = BB * NN;
    const int MT = (M + 127) / 128;          // 251
    const int SMEM = 3 * STAGE_B;            // 147456 B

    cudaFuncSetAttribute(hgemm<1>, cudaFuncAttributeMaxDynamicSharedMemorySize, SMEM);
    cudaFuncSetAttribute(hgemm<2>, cudaFuncAttributeMaxDynamicSharedMemorySize, SMEM);

    CUtensorMap mA1, mB1, mA2, mB2;
    make_map(&mA1, p,   CC, M,  128);
    make_map(&mB1, wt1, CC, CC, 256);
    make_map(&mA2, h1,  CC, M,  128);
    make_map(&mB2, wt2, CC, HH, 256);

    // prep
    transpose_half<<<dim3(CC/32, CC/32), dim3(32,8)>>>(Wa1, wt1, CC, CC);
    transpose_half<<<dim3(CC/32, HH/32), dim3(32,8)>>>(Wa2, wt2, CC, HH);
    prod_kernel<<<M, 256>>>(x, p);

    // h1 = relu(p @ Wa1 + ba1)   [half out]  — unique pairs only
    hgemm<1><<<dim3(CC/256, MT), 256, SMEM>>>(mA1, mB1, ba1, h1, nullptr, nullptr, M, CC, CC);
    // s partials (h2 never materialized)
    hgemm<2><<<dim3(HH/256, MT), 256, SMEM>>>(mA2, mB2, ba2, nullptr, Wa3, spart, M, CC, HH);

    agg_kernel<<<MR, 256>>>(x, spart, ba3, (const float*)d_in[1], (const float*)d_in[2], at, mt);

    const int MRT = (MR + 127) / 128; // 6
    mma_gemm<<<dim3(CC/128, MRT, 2), 256>>>(
        at, mt, (const float*)d_in[9], (const float*)d_in[13],
        (const float*)d_in[10], (const float*)d_in[14],
        t1a, t1m, nullptr, MR, CC, CC, 0);
    mma_gemm<<<dim3(CC/128, MRT, 1), 256>>>(
        t1a, nullptr, (const float*)d_in[11], nullptr,
        (const float*)d_in[12], nullptr,
        out, nullptr, x, MR, CC, CC, 1);
    mma_gemm<<<dim3(CC/128, MRT, 1), 256>>>(
        t1m, nullptr, (const float*)d_in[15], nullptr,
        (const float*)d_in[16], nullptr,
        out, nullptr, out, MR, CC, CC, 2);
}

// round 12
// speedup vs baseline: 2.8658x; 1.1602x over previous
#include <cuda_runtime.h>
#include <cuda.h>
#include <cuda_fp16.h>
#include <cstdint>
#include <math.h>

#define BB 8
#define NN 89
#define CC 1024
#define HH 512
#define TRI (NN*(NN+1)/2)        // 4005 pairs (j<=i)
#define M_SYM (BB*TRI)           // 32040 unique edge rows

// Scratch
__device__ __half g_p [(size_t)M_SYM * CC];
__device__ __half g_h1[(size_t)M_SYM * CC];
__device__ float  g_spart[(size_t)8 * M_SYM];
__device__ __half g_wt1[CC*CC];
__device__ __half g_wt2[HH*CC];
__device__ float g_at[BB*NN*CC];
__device__ float g_mt[BB*NN*CC];
__device__ float g_t1a[BB*NN*CC];
__device__ float g_t1m[BB*NN*CC];
__device__ float g_t2a[BB*NN*CC];
__device__ float g_t2m[BB*NN*CC];

// ---------------------------------------------------------------------------
__device__ __forceinline__ unsigned f2tf32(float x){
    unsigned r; asm("cvt.rna.tf32.f32 %0, %1;" : "=r"(r) : "f"(x)); return r;
}
__device__ __forceinline__ float4 round4(float4 v){
    return make_float4(__uint_as_float(f2tf32(v.x)), __uint_as_float(f2tf32(v.y)),
                       __uint_as_float(f2tf32(v.z)), __uint_as_float(f2tf32(v.w)));
}
__device__ __forceinline__ uint32_t smem_u32(const void* p){
    uint32_t a;
    asm("{ .reg .u64 t; cvta.to.shared.u64 t, %1; cvt.u32.u64 %0, t; }" : "=r"(a) : "l"(p));
    return a;
}
__device__ __forceinline__ void hmma(float c[4], const uint32_t a[4], const uint32_t b[2]){
    asm volatile("mma.sync.aligned.m16n8k16.row.col.f32.f16.f16.f32 "
        "{%0,%1,%2,%3}, {%4,%5,%6,%7}, {%8,%9}, {%0,%1,%2,%3};"
        : "+f"(c[0]), "+f"(c[1]), "+f"(c[2]), "+f"(c[3])
        : "r"(a[0]), "r"(a[1]), "r"(a[2]), "r"(a[3]), "r"(b[0]), "r"(b[1]));
}
__device__ __forceinline__ void ldmx4(uint32_t a[4], uint32_t addr){
    asm volatile("ldmatrix.sync.aligned.m8n8.x4.shared.b16 {%0,%1,%2,%3}, [%4];"
        : "=r"(a[0]), "=r"(a[1]), "=r"(a[2]), "=r"(a[3]) : "r"(addr));
}
__device__ __forceinline__ uint32_t pack_half2(float a, float b){
    __half2 h = __floats2half2_rn(a, b);
    return *reinterpret_cast<uint32_t*>(&h);
}
__device__ __forceinline__ uint32_t sw128(uint32_t b){ return b ^ ((b >> 3) & 0x70u); }

__device__ __forceinline__ void mbar_init(uint32_t a, uint32_t c){
    asm volatile("mbarrier.init.shared.b64 [%0], %1;" :: "r"(a), "r"(c) : "memory");
}
__device__ __forceinline__ void mbar_expect(uint32_t a, uint32_t bytes){
    asm volatile("mbarrier.arrive.expect_tx.shared.b64 _, [%0], %1;" :: "r"(a), "r"(bytes) : "memory");
}
__device__ __forceinline__ void mbar_wait(uint32_t a, uint32_t par){
    asm volatile("{\n\t.reg .pred P;\n"
        "LW_%=:\n\t"
        "mbarrier.try_wait.parity.acquire.cta.shared::cta.b64 P, [%0], %1, 0x989680;\n\t"
        "@!P bra LW_%=;\n\t}" :: "r"(a), "r"(par) : "memory");
}
__device__ __forceinline__ void tma2d(uint32_t dst, const CUtensorMap* m, int cx, int cy, uint32_t mb){
    asm volatile("cp.async.bulk.tensor.2d.shared::cta.global.tile.mbarrier::complete_tx::bytes "
                 "[%0], [%1, {%2, %3}], [%4];"
                 :: "r"(dst), "l"(m), "r"(cx), "r"(cy), "r"(mb) : "memory");
}
__device__ __forceinline__ void tri_decode(int p, int& j, int& i){
    i = (int)((sqrtf(8.0f*p + 1.0f) - 1.0f) * 0.5f);
    while ((i+1)*(i+2)/2 <= p) i++;
    while (i*(i+1)/2 > p) i--;
    j = p - i*(i+1)/2;
}

// ---------------------------------------------------------------------------
__global__ void __launch_bounds__(256) prod_kernel(const float* __restrict__ x, __half* __restrict__ p){
    const int row = blockIdx.x, seg = threadIdx.x;
    int b = row / TRI, pr = row - b*TRI;
    int j, i; tri_decode(pr, j, i);
    const float4 vj = ((const float4*)(x + (size_t)(b*NN + j)*CC))[seg];
    const float4 vi = ((const float4*)(x + (size_t)(b*NN + i)*CC))[seg];
    uint2 pk = make_uint2(pack_half2(vj.x*vi.x, vj.y*vi.y),
                          pack_half2(vj.z*vi.z, vj.w*vi.w));
    ((uint2*)p)[(size_t)row * 256 + seg] = pk;
}

__global__ void transpose_half(const float* __restrict__ W, __half* __restrict__ Wt, int K, int N){
    __shared__ float tile[32][33];
    int k0 = blockIdx.x*32, n0 = blockIdx.y*32;
    int tx = threadIdx.x, ty = threadIdx.y;
    #pragma unroll
    for (int r = 0; r < 32; r += 8)
        tile[ty + r][tx] = W[(size_t)(k0 + ty + r)*N + n0 + tx];
    __syncthreads();
    #pragma unroll
    for (int r = 0; r < 32; r += 8)
        Wt[(size_t)(n0 + ty + r)*K + k0 + tx] = __float2half(tile[tx][ty + r]);
}

// ---------------------------------------------------------------------------
// FP16 HMMA GEMM v6: CTA 128x256, BK=64 (128B swizzled rows), TMA staging,
// 4-stage mbarrier pipeline, 8 warps (2x4), warp tile 64x64.
//   MODE 1: C half = relu(acc+bias)
//   MODE 2: spart[col][r] = dot(relu(acc+bias), wvec)
// ---------------------------------------------------------------------------
#define BK 64
#define STAGES 4
#define A_ST_B 16384            // 128 rows x 128B
#define B_ST_B 32768            // 256 rows x 128B
#define STAGE_B (A_ST_B + B_ST_B)

template<int MODE>
__global__ void __launch_bounds__(256, 1) hgemm(
    const __grid_constant__ CUtensorMap mapA,
    const __grid_constant__ CUtensorMap mapB,
    const float* __restrict__ bias, void* __restrict__ Cout,
    const float* __restrict__ wvec, float* __restrict__ spart,
    int M, int K, int N)
{
    extern __shared__ __align__(1024) char sh[];
    __shared__ __align__(8) unsigned long long mbar[STAGES];

    const int t = threadIdx.x, warp = t >> 5, lane = t & 31;
    const int g = lane >> 2, tig = lane & 3;
    const int wm = (warp >> 2) * 64, wn = (warp & 3) * 64;
    const int mBase = blockIdx.y * 128, nBase = blockIdx.x * 256;

    const uint32_t uS = smem_u32(sh);
    const uint32_t uMB = smem_u32(&mbar[0]);
    const int laneR = lane & 15, laneK = (lane >> 4) << 3;
    const int bg4 = lane >> 3, br = lane & 7;

    if (t == 0){
        #pragma unroll
        for (int s = 0; s < STAGES; s++) mbar_init(uMB + s*8, 1);
        asm volatile("fence.proxy.async.shared::cta;" ::: "memory");
    }
    __syncthreads();

    const int KT = K / BK;   // 16
    if (t == 0){
        #pragma unroll
        for (int s = 0; s < STAGES - 1; s++){
            mbar_expect(uMB + s*8, STAGE_B);
            tma2d(uS + s*STAGE_B,          &mapA, s*BK, mBase, uMB + s*8);
            tma2d(uS + s*STAGE_B + A_ST_B, &mapB, s*BK, nBase, uMB + s*8);
        }
    }

    float acc[4][8][4];
    #pragma unroll
    for (int mi = 0; mi < 4; mi++)
        #pragma unroll
        for (int ni = 0; ni < 8; ni++)
            #pragma unroll
            for (int q = 0; q < 4; q++) acc[mi][ni][q] = 0.f;

    int ph[STAGES] = {0, 0, 0, 0};
    for (int kt = 0; kt < KT; kt++){
        const int b = kt % STAGES;
        mbar_wait(uMB + b*8, ph[b]); ph[b] ^= 1;

        const uint32_t uA = uS + (uint32_t)(b * STAGE_B);
        const uint32_t uB = uA + A_ST_B;

        #pragma unroll
        for (int ko = 0; ko < BK; ko += 16){
            uint32_t af[4][4], bf[8][2];
            #pragma unroll
            for (int mi = 0; mi < 4; mi++){
                uint32_t byte = (uint32_t)((wm + mi*16 + laneR)*128 + (ko + laneK)*2);
                ldmx4(af[mi], uA + sw128(byte));
            }
            #pragma unroll
            for (int nq = 0; nq < 4; nq++){
                uint32_t r4[4];
                int n = wn + nq*16 + (bg4 >> 1)*8 + br;
                int k = ko + (bg4 & 1)*8;
                uint32_t byte = (uint32_t)(n*128 + k*2);
                ldmx4(r4, uB + sw128(byte));
                bf[nq*2  ][0] = r4[0]; bf[nq*2  ][1] = r4[1];
                bf[nq*2+1][0] = r4[2]; bf[nq*2+1][1] = r4[3];
            }
            #pragma unroll
            for (int mi = 0; mi < 4; mi++)
                #pragma unroll
                for (int ni = 0; ni < 8; ni++)
                    hmma(acc[mi][ni], af[mi], bf[ni]);
        }

        __syncthreads();
        if (t == 0 && kt + STAGES - 1 < KT){
            const int bp = (kt + STAGES - 1) % STAGES;
            mbar_expect(uMB + bp*8, STAGE_B);
            tma2d(uS + bp*STAGE_B,          &mapA, (kt+STAGES-1)*BK, mBase, uMB + bp*8);
            tma2d(uS + bp*STAGE_B + A_ST_B, &mapB, (kt+STAGES-1)*BK, nBase, uMB + bp*8);
        }
    }

    if (MODE == 1){
        #pragma unroll
        for (int mi = 0; mi < 4; mi++)
            #pragma unroll
            for (int ni = 0; ni < 8; ni++){
                const int cb = nBase + wn + ni*8 + 2*tig;
                const float2 bs = *(const float2*)(bias + cb);
                #pragma unroll
                for (int hh = 0; hh < 2; hh++){
                    const int r = mBase + wm + mi*16 + g + hh*8;
                    if (r >= M) continue;
                    float z0 = fmaxf(acc[mi][ni][hh*2+0] + bs.x, 0.f);
                    float z1 = fmaxf(acc[mi][ni][hh*2+1] + bs.y, 0.f);
                    *(uint32_t*)((__half*)Cout + (size_t)r * N + cb) = pack_half2(z0, z1);
                }
            }
    } else {
        float rs[4][2];
        #pragma unroll
        for (int mi = 0; mi < 4; mi++){ rs[mi][0] = 0.f; rs[mi][1] = 0.f; }
        #pragma unroll
        for (int mi = 0; mi < 4; mi++)
            #pragma unroll
            for (int ni = 0; ni < 8; ni++){
                const int cb = nBase + wn + ni*8 + 2*tig;
                const float2 bs = *(const float2*)(bias + cb);
                const float2 wv = *(const float2*)(wvec + cb);
                #pragma unroll
                for (int hh = 0; hh < 2; hh++){
                    float z0 = fmaxf(acc[mi][ni][hh*2+0] + bs.x, 0.f);
                    float z1 = fmaxf(acc[mi][ni][hh*2+1] + bs.y, 0.f);
                    rs[mi][hh] += z0*wv.x + z1*wv.y;
                }
            }
        const int col = blockIdx.x * 4 + (warp & 3);
        #pragma unroll
        for (int mi = 0; mi < 4; mi++)
            #pragma unroll
            for (int hh = 0; hh < 2; hh++){
                float v = rs[mi][hh];
                v += __shfl_xor_sync(0xffffffffu, v, 1);
                v += __shfl_xor_sync(0xffffffffu, v, 2);
                const int r = mBase + wm + mi*16 + g + hh*8;
                if (tig == 0 && r < M)
                    spart[(size_t)col * M_SYM + r] = v;
            }
    }
}

// ---------------------------------------------------------------------------
// legacy tf32 GEMM for small 712-row GEMMs; blockIdx.z merges pairs.
// mode 0: relu(acc+bias), mode 3: acc+bias (no relu)
// ---------------------------------------------------------------------------
__device__ __forceinline__ void mma_frag(float c[4], const unsigned a[4], const unsigned b[2]){
    asm volatile("mma.sync.aligned.m16n8k8.row.col.f32.tf32.tf32.f32 "
        "{%0,%1,%2,%3}, {%4,%5,%6,%7}, {%8,%9}, {%0,%1,%2,%3};\n"
        : "+f"(c[0]), "+f"(c[1]), "+f"(c[2]), "+f"(c[3])
        : "r"(a[0]), "r"(a[1]), "r"(a[2]), "r"(a[3]), "r"(b[0]), "r"(b[1]));
}
__global__ void __launch_bounds__(256) mma_gemm(
    const float* __restrict__ A0, const float* __restrict__ A1,
    const float* __restrict__ B0, const float* __restrict__ B1,
    const float* __restrict__ bias0, const float* __restrict__ bias1,
    float* __restrict__ C0, float* __restrict__ C1,
    int M, int K, int Ncols, int mode)
{
    const float* A    = blockIdx.z ? A1 : A0;
    const float* Bm   = blockIdx.z ? B1 : B0;
    const float* bias = blockIdx.z ? bias1 : bias0;
    float* Cmat       = blockIdx.z ? C1 : C0;

    __shared__ __align__(16) float As[2][16][136];
    __shared__ __align__(16) float Bs[2][16][136];
    const int t = threadIdx.x, warp = t >> 5, lane = t & 31;
    const int g = lane >> 2, tig = lane & 3;
    const int wm = (warp >> 2) * 64, wn = (warp & 3) * 32;
    const int mBase = blockIdx.y * 128, nBase = blockIdx.x * 128;
    const int arow = t >> 2, akq = (t & 3) * 4;
    const int grow0 = mBase + arow, grow1 = grow0 + 64;
    const bool v0 = grow0 < M, v1 = grow1 < M;
    const float* ap0 = v0 ? A + (size_t)grow0 * K : nullptr;
    const float* ap1 = v1 ? A + (size_t)grow1 * K : nullptr;
    const int bkr = t >> 5, bnc = (t & 31) * 4;
    float4 a0s, a1s, b0s, b1s;
    auto load_g = [&](int k0){
        const float4 z = make_float4(0,0,0,0);
        a0s = v0 ? *(const float4*)(ap0 + k0 + akq) : z;
        a1s = v1 ? *(const float4*)(ap1 + k0 + akq) : z;
        b0s = *(const float4*)(Bm + (size_t)(k0 + bkr    ) * Ncols + nBase + bnc);
        b1s = *(const float4*)(Bm + (size_t)(k0 + bkr + 8) * Ncols + nBase + bnc);
    };
    auto store_s = [&](int buf){
        float4 c0 = round4(a0s), c1 = round4(a1s);
        As[buf][akq+0][arow] = c0.x; As[buf][akq+1][arow] = c0.y;
        As[buf][akq+2][arow] = c0.z; As[buf][akq+3][arow] = c0.w;
        As[buf][akq+0][arow+64] = c1.x; As[buf][akq+1][arow+64] = c1.y;
        As[buf][akq+2][arow+64] = c1.z; As[buf][akq+3][arow+64] = c1.w;
        *(float4*)&Bs[buf][bkr][bnc]     = round4(b0s);
        *(float4*)&Bs[buf][bkr + 8][bnc] = round4(b1s);
    };
    float acc[4][4][4];
    #pragma unroll
    for (int mi = 0; mi < 4; mi++)
        #pragma unroll
        for (int ni = 0; ni < 4; ni++)
            #pragma unroll
            for (int q = 0; q < 4; q++) acc[mi][ni][q] = 0.f;
    load_g(0); store_s(0); __syncthreads();
    const int KT = K / 16;
    for (int kt = 0; kt < KT; kt++){
        const int cur = kt & 1;
        if (kt + 1 < KT) load_g((kt + 1) * 16);
        #pragma unroll
        for (int ko = 0; ko < 16; ko += 8){
            unsigned af[4][4], bf[4][2];
            #pragma unroll
            for (int mi = 0; mi < 4; mi++){
                const int m0 = wm + mi*16 + g;
                af[mi][0] = __float_as_uint(As[cur][ko + tig    ][m0    ]);
                af[mi][1] = __float_as_uint(As[cur][ko + tig    ][m0 + 8]);
                af[mi][2] = __float_as_uint(As[cur][ko + tig + 4][m0    ]);
                af[mi][3] = __float_as_uint(As[cur][ko + tig + 4][m0 + 8]);
            }
            #pragma unroll
            for (int ni = 0; ni < 4; ni++){
                const int n0 = wn + ni*8 + g;
                bf[ni][0] = __float_as_uint(Bs[cur][ko + tig    ][n0]);
                bf[ni][1] = __float_as_uint(Bs[cur][ko + tig + 4][n0]);
            }
            #pragma unroll
            for (int mi = 0; mi < 4; mi++)
                #pragma unroll
                for (int ni = 0; ni < 4; ni++)
                    mma_frag(acc[mi][ni], af[mi], bf[ni]);
        }
        if (kt + 1 < KT) store_s((kt + 1) & 1);
        __syncthreads();
    }
    #pragma unroll
    for (int mi = 0; mi < 4; mi++)
        #pragma unroll
        for (int ni = 0; ni < 4; ni++){
            const int cb = nBase + wn + ni*8 + 2*tig;
            const float2 bs = *(const float2*)(bias + cb);
            #pragma unroll
            for (int hh = 0; hh < 2; hh++){
                const int r = mBase + wm + mi*16 + g + hh*8;
                if (r >= M) continue;
                float z0 = acc[mi][ni][hh*2+0] + bs.x;
                float z1 = acc[mi][ni][hh*2+1] + bs.y;
                if (mode == 0){ z0 = fmaxf(z0, 0.f); z1 = fmaxf(z1, 0.f); }
                *(float2*)(Cmat + (size_t)r * Ncols + cb) = make_float2(z0, z1);
            }
        }
}

// ---------------------------------------------------------------------------
// combine: out = (x + t2a + t2m) / 3
// ---------------------------------------------------------------------------
__global__ void __launch_bounds__(256) combine_kernel(
    const float* __restrict__ x, const float* __restrict__ t2a,
    const float* __restrict__ t2m, float* __restrict__ out)
{
    size_t idx = (size_t)blockIdx.x * 256 + threadIdx.x;
    float4 xv = ((const float4*)x)[idx];
    float4 av = ((const float4*)t2a)[idx];
    float4 mv = ((const float4*)t2m)[idx];
    const float k = 1.f/3.f;
    ((float4*)out)[idx] = make_float4((xv.x+av.x+mv.x)*k, (xv.y+av.y+mv.y)*k,
                                      (xv.z+av.z+mv.z)*k, (xv.w+av.w+mv.w)*k);
}

// ---------------------------------------------------------------------------
// aggregation with fused s finalize (triangular s lookup)
// ---------------------------------------------------------------------------
__global__ void __launch_bounds__(256) agg_kernel(
    const float* __restrict__ x, const float* __restrict__ spart,
    const float* __restrict__ ba3,
    const float* __restrict__ adj_add, const float* __restrict__ adj_mod,
    float* __restrict__ at, float* __restrict__ mt)
{
    __shared__ float sv_sh[NN];
    int bi = blockIdx.x;
    int b = bi / NN, i = bi - b*NN;
    if (threadIdx.x < NN){
        int j = threadIdx.x;
        int lo = j <= i ? j : i;
        int hi = j <= i ? i : j;
        int row = b*TRI + hi*(hi+1)/2 + lo;
        float v = ba3[0];
        #pragma unroll
        for (int c = 0; c < 8; c++) v += spart[(size_t)c * M_SYM + row];
        sv_sh[j] = 1.f / (1.f + expf(-v));
    }
    __syncthreads();

    int f = threadIdx.x * 4;
    float4 aa = make_float4(0,0,0,0), mm = make_float4(0,0,0,0);
    for (int j = 0; j < NN; j++){
        float wa = sv_sh[j] * adj_add[j*NN + i];
        float wm = adj_mod[j*NN + i];
        float4 xv = *(const float4*)(x + (size_t)(b*NN + j)*CC + f);
        aa.x = fmaf(wa, xv.x, aa.x); aa.y = fmaf(wa, xv.y, aa.y);
        aa.z = fmaf(wa, xv.z, aa.z); aa.w = fmaf(wa, xv.w, aa.w);
        mm.x = fmaf(wm, xv.x, mm.x); mm.y = fmaf(wm, xv.y, mm.y);
        mm.z = fmaf(wm, xv.z, mm.z); mm.w = fmaf(wm, xv.w, mm.w);
    }
    float4 xv = *(const float4*)(x + (size_t)bi * CC + f);
    mm.x *= xv.x; mm.y *= xv.y; mm.z *= xv.z; mm.w *= xv.w;
    *(float4*)(at + (size_t)bi * CC + f) = aa;
    *(float4*)(mt + (size_t)bi * CC + f) = mm;
}

// ---------------------------------------------------------------------------
// host
// ---------------------------------------------------------------------------
typedef CUresult (*EncodeFn)(CUtensorMap*, CUtensorMapDataType, cuuint32_t, void*,
    const cuuint64_t*, const cuuint64_t*, const cuuint32_t*, const cuuint32_t*,
    CUtensorMapInterleave, CUtensorMapSwizzle, CUtensorMapL2promotion, CUtensorMapFloatOOBfill);

static EncodeFn get_encoder(){
    static EncodeFn fn = nullptr;
    if (!fn){
        cudaDriverEntryPointQueryResult qr;
#if CUDART_VERSION >= 12050
        cudaGetDriverEntryPointByVersion("cuTensorMapEncodeTiled", (void**)&fn, 12000,
                                         cudaEnableDefault, &qr);
#else
        cudaGetDriverEntryPoint("cuTensorMapEncodeTiled", (void**)&fn, cudaEnableDefault, &qr);
#endif
    }
    return fn;
}
static void make_map(CUtensorMap* m, void* ptr, uint64_t kdim, uint64_t rows, uint32_t boxRows){
    cuuint64_t dims[2] = {kdim, rows};
    cuuint64_t strides[1] = {kdim * 2};
    cuuint32_t box[2] = {BK, boxRows};
    cuuint32_t es[2] = {1, 1};
    get_encoder()(m, CU_TENSOR_MAP_DATA_TYPE_FLOAT16, 2, ptr, dims, strides, box, es,
        CU_TENSOR_MAP_INTERLEAVE_NONE, CU_TENSOR_MAP_SWIZZLE_128B,
        CU_TENSOR_MAP_L2_PROMOTION_L2_128B, CU_TENSOR_MAP_FLOAT_OOB_FILL_NONE);
}

extern "C" void kernel_launch(void* const* d_in, const int* in_sizes, int n_in,
                              void* d_out, int out_size)
{
    const float* x    = (const float*)d_in[0];
    const float* Wa1  = (const float*)d_in[3];
    const float* ba1  = (const float*)d_in[4];
    const float* Wa2  = (const float*)d_in[5];
    const float* ba2  = (const float*)d_in[6];
    const float* Wa3  = (const float*)d_in[7];
    const float* ba3  = (const float*)d_in[8];
    float* out = (float*)d_out;

    __half *p, *h1, *wt1, *wt2;
    float *spart, *at, *mt, *t1a, *t1m, *t2a, *t2m;
    cudaGetSymbolAddress((void**)&p,    g_p);
    cudaGetSymbolAddress((void**)&h1,   g_h1);
    cudaGetSymbolAddress((void**)&spart,g_spart);
    cudaGetSymbolAddress((void**)&wt1,  g_wt1);
    cudaGetSymbolAddress((void**)&wt2,  g_wt2);
    cudaGetSymbolAddress((void**)&at,   g_at);
    cudaGetSymbolAddress((void**)&mt,   g_mt);
    cudaGetSymbolAddress((void**)&t1a,  g_t1a);
    cudaGetSymbolAddress((void**)&t1m,  g_t1m);
    cudaGetSymbolAddress((void**)&t2a,  g_t2a);
    cudaGetSymbolAddress((void**)&t2m,  g_t2m);

    const int M = M_SYM, MR = BB * NN;
    const int MT = (M + 127) / 128;          // 251
    const int SMEM = STAGES * STAGE_B;       // 196608 B

    cudaFuncSetAttribute(hgemm<1>, cudaFuncAttributeMaxDynamicSharedMemorySize, SMEM);
    cudaFuncSetAttribute(hgemm<2>, cudaFuncAttributeMaxDynamicSharedMemorySize, SMEM);

    CUtensorMap mA1, mB1, mA2, mB2;
    make_map(&mA1, p,   CC, M,  128);
    make_map(&mB1, wt1, CC, CC, 256);
    make_map(&mA2, h1,  CC, M,  128);
    make_map(&mB2, wt2, CC, HH, 256);

    // prep
    transpose_half<<<dim3(CC/32, CC/32), dim3(32,8)>>>(Wa1, wt1, CC, CC);
    transpose_half<<<dim3(CC/32, HH/32), dim3(32,8)>>>(Wa2, wt2, CC, HH);
    prod_kernel<<<M, 256>>>(x, p);

    // h1 = relu(p @ Wa1 + ba1)   [half out]
    hgemm<1><<<dim3(CC/256, MT), 256, SMEM>>>(mA1, mB1, ba1, h1, nullptr, nullptr, M, CC, CC);
    // s partials
    hgemm<2><<<dim3(HH/256, MT), 256, SMEM>>>(mA2, mB2, ba2, nullptr, Wa3, spart, M, CC, HH);

    agg_kernel<<<MR, 256>>>(x, spart, ba3, (const float*)d_in[1], (const float*)d_in[2], at, mt);

    const int MRT = (MR + 127) / 128; // 6
    // layer-1 pair (relu)
    mma_gemm<<<dim3(CC/128, MRT, 2), 256>>>(
        at, mt, (const float*)d_in[9], (const float*)d_in[13],
        (const float*)d_in[10], (const float*)d_in[14],
        t1a, t1m, MR, CC, CC, 0);
    // layer-2 pair (no relu) -> t2a, t2m
    mma_gemm<<<dim3(CC/128, MRT, 2), 256>>>(
        t1a, t1m, (const float*)d_in[11], (const float*)d_in[15],
        (const float*)d_in[12], (const float*)d_in[16],
        t2a, t2m, MR, CC, CC, 3);
    // out = (x + t2a + t2m)/3
    combine_kernel<<<(MR*CC/4 + 255)/256, 256>>>(x, t2a, t2m, out);
}

// round 13
// speedup vs baseline: 3.2307x; 1.1273x over previous
#include <cuda_runtime.h>
#include <cuda.h>
#include <cuda_fp16.h>
#include <cstdint>
#include <math.h>

#define BB 8
#define NN 89
#define CC 1024
#define HH 512
#define TRI (NN*(NN+1)/2)        // 4005 pairs (j<=i)
#define M_SYM (BB*TRI)           // 32040 unique edge rows
#define MR (BB*NN)               // 712

// Scratch
__device__ __half g_p [(size_t)M_SYM * CC];
__device__ __half g_h1[(size_t)M_SYM * CC];
__device__ float  g_spart[(size_t)8 * M_SYM];
__device__ __half g_wt1[CC*CC];
__device__ __half g_wt2[HH*CC];
__device__ __half g_wadd1[CC*CC];
__device__ __half g_wadd2[CC*CC];
__device__ __half g_wmod1[CC*CC];
__device__ __half g_wmod2[CC*CC];
__device__ __half g_at[MR*CC];
__device__ __half g_mt[MR*CC];
__device__ __half g_t1a[MR*CC];
__device__ __half g_t1m[MR*CC];
__device__ float  g_t2a[MR*CC];
__device__ float  g_t2m[MR*CC];

// ---------------------------------------------------------------------------
__device__ __forceinline__ uint32_t smem_u32(const void* p){
    uint32_t a;
    asm("{ .reg .u64 t; cvta.to.shared.u64 t, %1; cvt.u32.u64 %0, t; }" : "=r"(a) : "l"(p));
    return a;
}
__device__ __forceinline__ void hmma(float c[4], const uint32_t a[4], const uint32_t b[2]){
    asm volatile("mma.sync.aligned.m16n8k16.row.col.f32.f16.f16.f32 "
        "{%0,%1,%2,%3}, {%4,%5,%6,%7}, {%8,%9}, {%0,%1,%2,%3};"
        : "+f"(c[0]), "+f"(c[1]), "+f"(c[2]), "+f"(c[3])
        : "r"(a[0]), "r"(a[1]), "r"(a[2]), "r"(a[3]), "r"(b[0]), "r"(b[1]));
}
__device__ __forceinline__ void ldmx4(uint32_t a[4], uint32_t addr){
    asm volatile("ldmatrix.sync.aligned.m8n8.x4.shared.b16 {%0,%1,%2,%3}, [%4];"
        : "=r"(a[0]), "=r"(a[1]), "=r"(a[2]), "=r"(a[3]) : "r"(addr));
}
__device__ __forceinline__ uint32_t pack_half2(float a, float b){
    __half2 h = __floats2half2_rn(a, b);
    return *reinterpret_cast<uint32_t*>(&h);
}
__device__ __forceinline__ uint32_t sw128(uint32_t b){ return b ^ ((b >> 3) & 0x70u); }

__device__ __forceinline__ void mbar_init(uint32_t a, uint32_t c){
    asm volatile("mbarrier.init.shared.b64 [%0], %1;" :: "r"(a), "r"(c) : "memory");
}
__device__ __forceinline__ void mbar_expect(uint32_t a, uint32_t bytes){
    asm volatile("mbarrier.arrive.expect_tx.shared.b64 _, [%0], %1;" :: "r"(a), "r"(bytes) : "memory");
}
__device__ __forceinline__ void mbar_wait(uint32_t a, uint32_t par){
    asm volatile("{\n\t.reg .pred P;\n"
        "LW_%=:\n\t"
        "mbarrier.try_wait.parity.acquire.cta.shared::cta.b64 P, [%0], %1, 0x989680;\n\t"
        "@!P bra LW_%=;\n\t}" :: "r"(a), "r"(par) : "memory");
}
__device__ __forceinline__ void tma2d(uint32_t dst, const CUtensorMap* m, int cx, int cy, uint32_t mb){
    asm volatile("cp.async.bulk.tensor.2d.shared::cta.global.tile.mbarrier::complete_tx::bytes "
                 "[%0], [%1, {%2, %3}], [%4];"
                 :: "r"(dst), "l"(m), "r"(cx), "r"(cy), "r"(mb) : "memory");
}
__device__ __forceinline__ void tri_decode(int p, int& j, int& i){
    i = (int)((sqrtf(8.0f*p + 1.0f) - 1.0f) * 0.5f);
    while ((i+1)*(i+2)/2 <= p) i++;
    while (i*(i+1)/2 > p) i--;
    j = p - i*(i+1)/2;
}

// ---------------------------------------------------------------------------
__global__ void __launch_bounds__(256) prod_kernel(const float* __restrict__ x, __half* __restrict__ p){
    const int row = blockIdx.x, seg = threadIdx.x;
    int b = row / TRI, pr = row - b*TRI;
    int j, i; tri_decode(pr, j, i);
    const float4 vj = ((const float4*)(x + (size_t)(b*NN + j)*CC))[seg];
    const float4 vi = ((const float4*)(x + (size_t)(b*NN + i)*CC))[seg];
    uint2 pk = make_uint2(pack_half2(vj.x*vi.x, vj.y*vi.y),
                          pack_half2(vj.z*vi.z, vj.w*vi.w));
    ((uint2*)p)[(size_t)row * 256 + seg] = pk;
}

// one z-merged transpose for the five CxC weights
__global__ void transpose_cc(const float* __restrict__ W0, const float* __restrict__ W1,
                             const float* __restrict__ W2, const float* __restrict__ W3,
                             const float* __restrict__ W4,
                             __half* __restrict__ T0, __half* __restrict__ T1,
                             __half* __restrict__ T2, __half* __restrict__ T3,
                             __half* __restrict__ T4)
{
    const float* W; __half* T;
    switch (blockIdx.z){
        case 0: W = W0; T = T0; break;
        case 1: W = W1; T = T1; break;
        case 2: W = W2; T = T2; break;
        case 3: W = W3; T = T3; break;
        default: W = W4; T = T4; break;
    }
    __shared__ float tile[32][33];
    int k0 = blockIdx.x*32, n0 = blockIdx.y*32;
    int tx = threadIdx.x, ty = threadIdx.y;
    #pragma unroll
    for (int r = 0; r < 32; r += 8)
        tile[ty + r][tx] = W[(size_t)(k0 + ty + r)*CC + n0 + tx];
    __syncthreads();
    #pragma unroll
    for (int r = 0; r < 32; r += 8)
        T[(size_t)(n0 + ty + r)*CC + k0 + tx] = __float2half(tile[tx][ty + r]);
}

__global__ void transpose_half(const float* __restrict__ W, __half* __restrict__ Wt, int K, int N){
    __shared__ float tile[32][33];
    int k0 = blockIdx.x*32, n0 = blockIdx.y*32;
    int tx = threadIdx.x, ty = threadIdx.y;
    #pragma unroll
    for (int r = 0; r < 32; r += 8)
        tile[ty + r][tx] = W[(size_t)(k0 + ty + r)*N + n0 + tx];
    __syncthreads();
    #pragma unroll
    for (int r = 0; r < 32; r += 8)
        Wt[(size_t)(n0 + ty + r)*K + k0 + tx] = __float2half(tile[tx][ty + r]);
}

// ---------------------------------------------------------------------------
// FP16 HMMA GEMM: CTA 128x256, BK=64 (128B swizzled rows), TMA staging,
// 4-stage mbarrier pipeline, 8 warps (2x4), warp tile 64x64.
// blockIdx.z selects (mapA,mapB,bias,Cout) pair -> two GEMMs per launch.
//   MODE 1: C half = relu(acc+bias)
//   MODE 2: spart[col][r] = dot(relu(acc+bias), wvec)
//   MODE 4: C fp32 = acc+bias (no relu)
// ---------------------------------------------------------------------------
#define BK 64
#define STAGES 4
#define A_ST_B 16384
#define B_ST_B 32768
#define STAGE_B (A_ST_B + B_ST_B)

template<int MODE>
__global__ void __launch_bounds__(256, 1) hgemm(
    const __grid_constant__ CUtensorMap mA0, const __grid_constant__ CUtensorMap mB0,
    const __grid_constant__ CUtensorMap mA1, const __grid_constant__ CUtensorMap mB1,
    const float* __restrict__ bias0, const float* __restrict__ bias1,
    void* __restrict__ C0, void* __restrict__ C1,
    const float* __restrict__ wvec, float* __restrict__ spart,
    int M, int K, int N)
{
    extern __shared__ __align__(1024) char sh[];
    __shared__ __align__(8) unsigned long long mbar[STAGES];

    const CUtensorMap* mapA = blockIdx.z ? &mA1 : &mA0;
    const CUtensorMap* mapB = blockIdx.z ? &mB1 : &mB0;
    const float* bias = blockIdx.z ? bias1 : bias0;
    void* Cout        = blockIdx.z ? C1 : C0;

    const int t = threadIdx.x, warp = t >> 5, lane = t & 31;
    const int g = lane >> 2, tig = lane & 3;
    const int wm = (warp >> 2) * 64, wn = (warp & 3) * 64;
    const int mBase = blockIdx.y * 128, nBase = blockIdx.x * 256;

    const uint32_t uS = smem_u32(sh);
    const uint32_t uMB = smem_u32(&mbar[0]);
    const int laneR = lane & 15, laneK = (lane >> 4) << 3;
    const int bg4 = lane >> 3, br = lane & 7;

    if (t == 0){
        #pragma unroll
        for (int s = 0; s < STAGES; s++) mbar_init(uMB + s*8, 1);
        asm volatile("fence.proxy.async.shared::cta;" ::: "memory");
    }
    __syncthreads();

    const int KT = K / BK;
    if (t == 0){
        #pragma unroll
        for (int s = 0; s < STAGES - 1; s++){
            mbar_expect(uMB + s*8, STAGE_B);
            tma2d(uS + s*STAGE_B,          mapA, s*BK, mBase, uMB + s*8);
            tma2d(uS + s*STAGE_B + A_ST_B, mapB, s*BK, nBase, uMB + s*8);
        }
    }

    float acc[4][8][4];
    #pragma unroll
    for (int mi = 0; mi < 4; mi++)
        #pragma unroll
        for (int ni = 0; ni < 8; ni++)
            #pragma unroll
            for (int q = 0; q < 4; q++) acc[mi][ni][q] = 0.f;

    int ph[STAGES] = {0, 0, 0, 0};
    for (int kt = 0; kt < KT; kt++){
        const int b = kt % STAGES;
        mbar_wait(uMB + b*8, ph[b]); ph[b] ^= 1;

        const uint32_t uA = uS + (uint32_t)(b * STAGE_B);
        const uint32_t uB = uA + A_ST_B;

        #pragma unroll
        for (int ko = 0; ko < BK; ko += 16){
            uint32_t af[4][4], bf[8][2];
            #pragma unroll
            for (int mi = 0; mi < 4; mi++){
                uint32_t byte = (uint32_t)((wm + mi*16 + laneR)*128 + (ko + laneK)*2);
                ldmx4(af[mi], uA + sw128(byte));
            }
            #pragma unroll
            for (int nq = 0; nq < 4; nq++){
                uint32_t r4[4];
                int n = wn + nq*16 + (bg4 >> 1)*8 + br;
                int k = ko + (bg4 & 1)*8;
                uint32_t byte = (uint32_t)(n*128 + k*2);
                ldmx4(r4, uB + sw128(byte));
                bf[nq*2  ][0] = r4[0]; bf[nq*2  ][1] = r4[1];
                bf[nq*2+1][0] = r4[2]; bf[nq*2+1][1] = r4[3];
            }
            #pragma unroll
            for (int mi = 0; mi < 4; mi++)
                #pragma unroll
                for (int ni = 0; ni < 8; ni++)
                    hmma(acc[mi][ni], af[mi], bf[ni]);
        }

        __syncthreads();
        if (t == 0 && kt + STAGES - 1 < KT){
            const int bp = (kt + STAGES - 1) % STAGES;
            mbar_expect(uMB + bp*8, STAGE_B);
            tma2d(uS + bp*STAGE_B,          mapA, (kt+STAGES-1)*BK, mBase, uMB + bp*8);
            tma2d(uS + bp*STAGE_B + A_ST_B, mapB, (kt+STAGES-1)*BK, nBase, uMB + bp*8);
        }
    }

    if (MODE == 1 || MODE == 4){
        #pragma unroll
        for (int mi = 0; mi < 4; mi++)
            #pragma unroll
            for (int ni = 0; ni < 8; ni++){
                const int cb = nBase + wn + ni*8 + 2*tig;
                const float2 bs = *(const float2*)(bias + cb);
                #pragma unroll
                for (int hh = 0; hh < 2; hh++){
                    const int r = mBase + wm + mi*16 + g + hh*8;
                    if (r >= M) continue;
                    float z0 = acc[mi][ni][hh*2+0] + bs.x;
                    float z1 = acc[mi][ni][hh*2+1] + bs.y;
                    if (MODE == 1){
                        z0 = fmaxf(z0, 0.f); z1 = fmaxf(z1, 0.f);
                        *(uint32_t*)((__half*)Cout + (size_t)r * N + cb) = pack_half2(z0, z1);
                    } else {
                        *(float2*)((float*)Cout + (size_t)r * N + cb) = make_float2(z0, z1);
                    }
                }
            }
    } else {
        float rs[4][2];
        #pragma unroll
        for (int mi = 0; mi < 4; mi++){ rs[mi][0] = 0.f; rs[mi][1] = 0.f; }
        #pragma unroll
        for (int mi = 0; mi < 4; mi++)
            #pragma unroll
            for (int ni = 0; ni < 8; ni++){
                const int cb = nBase + wn + ni*8 + 2*tig;
                const float2 bs = *(const float2*)(bias + cb);
                const float2 wv = *(const float2*)(wvec + cb);
                #pragma unroll
                for (int hh = 0; hh < 2; hh++){
                    float z0 = fmaxf(acc[mi][ni][hh*2+0] + bs.x, 0.f);
                    float z1 = fmaxf(acc[mi][ni][hh*2+1] + bs.y, 0.f);
                    rs[mi][hh] += z0*wv.x + z1*wv.y;
                }
            }
        const int col = blockIdx.x * 4 + (warp & 3);
        #pragma unroll
        for (int mi = 0; mi < 4; mi++)
            #pragma unroll
            for (int hh = 0; hh < 2; hh++){
                float v = rs[mi][hh];
                v += __shfl_xor_sync(0xffffffffu, v, 1);
                v += __shfl_xor_sync(0xffffffffu, v, 2);
                const int r = mBase + wm + mi*16 + g + hh*8;
                if (tig == 0 && r < M)
                    spart[(size_t)col * M_SYM + r] = v;
            }
    }
}

// ---------------------------------------------------------------------------
// combine: out = (x + t2a + t2m) / 3
// ---------------------------------------------------------------------------
__global__ void __launch_bounds__(256) combine_kernel(
    const float* __restrict__ x, const float* __restrict__ t2a,
    const float* __restrict__ t2m, float* __restrict__ out)
{
    size_t idx = (size_t)blockIdx.x * 256 + threadIdx.x;
    float4 xv = ((const float4*)x)[idx];
    float4 av = ((const float4*)t2a)[idx];
    float4 mv = ((const float4*)t2m)[idx];
    const float k = 1.f/3.f;
    ((float4*)out)[idx] = make_float4((xv.x+av.x+mv.x)*k, (xv.y+av.y+mv.y)*k,
                                      (xv.z+av.z+mv.z)*k, (xv.w+av.w+mv.w)*k);
}

// ---------------------------------------------------------------------------
// aggregation with fused s finalize (triangular s lookup); half outputs
// ---------------------------------------------------------------------------
__global__ void __launch_bounds__(256) agg_kernel(
    const float* __restrict__ x, const float* __restrict__ spart,
    const float* __restrict__ ba3,
    const float* __restrict__ adj_add, const float* __restrict__ adj_mod,
    __half* __restrict__ at, __half* __restrict__ mt)
{
    __shared__ float sv_sh[NN];
    int bi = blockIdx.x;
    int b = bi / NN, i = bi - b*NN;
    if (threadIdx.x < NN){
        int j = threadIdx.x;
        int lo = j <= i ? j : i;
        int hi = j <= i ? i : j;
        int row = b*TRI + hi*(hi+1)/2 + lo;
        float v = ba3[0];
        #pragma unroll
        for (int c = 0; c < 8; c++) v += spart[(size_t)c * M_SYM + row];
        sv_sh[j] = 1.f / (1.f + expf(-v));
    }
    __syncthreads();

    int f = threadIdx.x * 4;
    float4 aa = make_float4(0,0,0,0), mm = make_float4(0,0,0,0);
    for (int j = 0; j < NN; j++){
        float wa = sv_sh[j] * adj_add[j*NN + i];
        float wm = adj_mod[j*NN + i];
        float4 xv = *(const float4*)(x + (size_t)(b*NN + j)*CC + f);
        aa.x = fmaf(wa, xv.x, aa.x); aa.y = fmaf(wa, xv.y, aa.y);
        aa.z = fmaf(wa, xv.z, aa.z); aa.w = fmaf(wa, xv.w, aa.w);
        mm.x = fmaf(wm, xv.x, mm.x); mm.y = fmaf(wm, xv.y, mm.y);
        mm.z = fmaf(wm, xv.z, mm.z); mm.w = fmaf(wm, xv.w, mm.w);
    }
    float4 xv = *(const float4*)(x + (size_t)bi * CC + f);
    mm.x *= xv.x; mm.y *= xv.y; mm.z *= xv.z; mm.w *= xv.w;
    ((uint2*)(at + (size_t)bi * CC))[threadIdx.x] =
        make_uint2(pack_half2(aa.x, aa.y), pack_half2(aa.z, aa.w));
    ((uint2*)(mt + (size_t)bi * CC))[threadIdx.x] =
        make_uint2(pack_half2(mm.x, mm.y), pack_half2(mm.z, mm.w));
}

// ---------------------------------------------------------------------------
// host
// ---------------------------------------------------------------------------
typedef CUresult (*EncodeFn)(CUtensorMap*, CUtensorMapDataType, cuuint32_t, void*,
    const cuuint64_t*, const cuuint64_t*, const cuuint32_t*, const cuuint32_t*,
    CUtensorMapInterleave, CUtensorMapSwizzle, CUtensorMapL2promotion, CUtensorMapFloatOOBfill);

static EncodeFn get_encoder(){
    static EncodeFn fn = nullptr;
    if (!fn){
        cudaDriverEntryPointQueryResult qr;
#if CUDART_VERSION >= 12050
        cudaGetDriverEntryPointByVersion("cuTensorMapEncodeTiled", (void**)&fn, 12000,
                                         cudaEnableDefault, &qr);
#else
        cudaGetDriverEntryPoint("cuTensorMapEncodeTiled", (void**)&fn, cudaEnableDefault, &qr);
#endif
    }
    return fn;
}
static void make_map(CUtensorMap* m, void* ptr, uint64_t kdim, uint64_t rows, uint32_t boxRows){
    cuuint64_t dims[2] = {kdim, rows};
    cuuint64_t strides[1] = {kdim * 2};
    cuuint32_t box[2] = {BK, boxRows};
    cuuint32_t es[2] = {1, 1};
    get_encoder()(m, CU_TENSOR_MAP_DATA_TYPE_FLOAT16, 2, ptr, dims, strides, box, es,
        CU_TENSOR_MAP_INTERLEAVE_NONE, CU_TENSOR_MAP_SWIZZLE_128B,
        CU_TENSOR_MAP_L2_PROMOTION_L2_128B, CU_TENSOR_MAP_FLOAT_OOB_FILL_NONE);
}

extern "C" void kernel_launch(void* const* d_in, const int* in_sizes, int n_in,
                              void* d_out, int out_size)
{
    const float* x    = (const float*)d_in[0];
    const float* Wa1  = (const float*)d_in[3];
    const float* ba1  = (const float*)d_in[4];
    const float* Wa2  = (const float*)d_in[5];
    const float* ba2  = (const float*)d_in[6];
    const float* Wa3  = (const float*)d_in[7];
    const float* ba3  = (const float*)d_in[8];
    const float* Wadd1 = (const float*)d_in[9];
    const float* badd1 = (const float*)d_in[10];
    const float* Wadd2 = (const float*)d_in[11];
    const float* badd2 = (const float*)d_in[12];
    const float* Wmod1 = (const float*)d_in[13];
    const float* bmod1 = (const float*)d_in[14];
    const float* Wmod2 = (const float*)d_in[15];
    const float* bmod2 = (const float*)d_in[16];
    float* out = (float*)d_out;

    __half *p, *h1, *wt1, *wt2, *wadd1, *wadd2, *wmod1, *wmod2, *at, *mt, *t1a, *t1m;
    float *spart, *t2a, *t2m;
    cudaGetSymbolAddress((void**)&p,    g_p);
    cudaGetSymbolAddress((void**)&h1,   g_h1);
    cudaGetSymbolAddress((void**)&spart,g_spart);
    cudaGetSymbolAddress((void**)&wt1,  g_wt1);
    cudaGetSymbolAddress((void**)&wt2,  g_wt2);
    cudaGetSymbolAddress((void**)&wadd1,g_wadd1);
    cudaGetSymbolAddress((void**)&wadd2,g_wadd2);
    cudaGetSymbolAddress((void**)&wmod1,g_wmod1);
    cudaGetSymbolAddress((void**)&wmod2,g_wmod2);
    cudaGetSymbolAddress((void**)&at,   g_at);
    cudaGetSymbolAddress((void**)&mt,   g_mt);
    cudaGetSymbolAddress((void**)&t1a,  g_t1a);
    cudaGetSymbolAddress((void**)&t1m,  g_t1m);
    cudaGetSymbolAddress((void**)&t2a,  g_t2a);
    cudaGetSymbolAddress((void**)&t2m,  g_t2m);

    const int M = M_SYM;
    const int MT = (M + 127) / 128;          // 251
    const int MRT = (MR + 127) / 128;        // 6
    const int SMEM = STAGES * STAGE_B;       // 196608 B

    cudaFuncSetAttribute(hgemm<1>, cudaFuncAttributeMaxDynamicSharedMemorySize, SMEM);
    cudaFuncSetAttribute(hgemm<2>, cudaFuncAttributeMaxDynamicSharedMemorySize, SMEM);
    cudaFuncSetAttribute(hgemm<4>, cudaFuncAttributeMaxDynamicSharedMemorySize, SMEM);

    CUtensorMap mA1, mB1, mA2, mB2, mAT, mMT, mBadd1, mBmod1, mT1A, mT1M, mBadd2, mBmod2;
    make_map(&mA1, p,   CC, M,  128);
    make_map(&mB1, wt1, CC, CC, 256);
    make_map(&mA2, h1,  CC, M,  128);
    make_map(&mB2, wt2, CC, HH, 256);
    make_map(&mAT,   at,    CC, MR, 128);
    make_map(&mMT,   mt,    CC, MR, 128);
    make_map(&mBadd1,wadd1, CC, CC, 256);
    make_map(&mBmod1,wmod1, CC, CC, 256);
    make_map(&mT1A,  t1a,   CC, MR, 128);
    make_map(&mT1M,  t1m,   CC, MR, 128);
    make_map(&mBadd2,wadd2, CC, CC, 256);
    make_map(&mBmod2,wmod2, CC, CC, 256);

    // prep: transposes + edge products
    transpose_cc<<<dim3(32, 32, 5), dim3(32,8)>>>(
        Wa1, Wadd1, Wmod1, Wadd2, Wmod2, wt1, wadd1, wmod1, wadd2, wmod2);
    transpose_half<<<dim3(CC/32, HH/32), dim3(32,8)>>>(Wa2, wt2, CC, HH);
    prod_kernel<<<M, 256>>>(x, p);

    // h1 = relu(p @ Wa1 + ba1)   [half out]
    hgemm<1><<<dim3(CC/256, MT, 1), 256, SMEM>>>(
        mA1, mB1, mA1, mB1, ba1, ba1, h1, h1, nullptr, nullptr, M, CC, CC);
    // s partials
    hgemm<2><<<dim3(HH/256, MT, 1), 256, SMEM>>>(
        mA2, mB2, mA2, mB2, ba2, ba2, nullptr, nullptr, Wa3, spart, M, CC, HH);

    agg_kernel<<<MR, 256>>>(x, spart, ba3, (const float*)d_in[1], (const float*)d_in[2], at, mt);

    // layer-1 pair (relu, half out)
    hgemm<1><<<dim3(CC/256, MRT, 2), 256, SMEM>>>(
        mAT, mBadd1, mMT, mBmod1, badd1, bmod1, t1a, t1m, nullptr, nullptr, MR, CC, CC);
    // layer-2 pair (no relu, fp32 out)
    hgemm<4><<<dim3(CC/256, MRT, 2), 256, SMEM>>>(
        mT1A, mBadd2, mT1M, mBmod2, badd2, bmod2, t2a, t2m, nullptr, nullptr, MR, CC, CC);

    combine_kernel<<<(MR*CC/4 + 255)/256, 256>>>(x, t2a, t2m, out);
}

// round 14
// speedup vs baseline: 3.2363x; 1.0017x over previous
#include <cuda_runtime.h>
#include <cuda.h>
#include <cuda_fp16.h>
#include <cstdint>
#include <math.h>

#define BB 8
#define NN 89
#define CC 1024
#define HH 512
#define TRI (NN*(NN+1)/2)        // 4005 pairs (j<=i)
#define M_SYM (BB*TRI)           // 32040 unique edge rows
#define MR (BB*NN)               // 712

// Scratch
__device__ __half g_p [(size_t)M_SYM * CC];
__device__ __half g_h1[(size_t)M_SYM * CC];
__device__ float  g_spart[(size_t)8 * M_SYM];
__device__ __half g_wt1[CC*CC];
__device__ __half g_wt2[HH*CC];
__device__ __half g_wadd1[CC*CC];
__device__ __half g_wadd2[CC*CC];
__device__ __half g_wmod1[CC*CC];
__device__ __half g_wmod2[CC*CC];
__device__ __half g_at[MR*CC];
__device__ __half g_mt[MR*CC];
__device__ __half g_t1a[MR*CC];
__device__ __half g_t1m[MR*CC];
__device__ float  g_t2a[MR*CC];
__device__ float  g_t2m[MR*CC];

// ---------------------------------------------------------------------------
__device__ __forceinline__ uint32_t smem_u32(const void* p){
    uint32_t a;
    asm("{ .reg .u64 t; cvta.to.shared.u64 t, %1; cvt.u32.u64 %0, t; }" : "=r"(a) : "l"(p));
    return a;
}
__device__ __forceinline__ void hmma(float c[4], const uint32_t a[4], const uint32_t b[2]){
    asm volatile("mma.sync.aligned.m16n8k16.row.col.f32.f16.f16.f32 "
        "{%0,%1,%2,%3}, {%4,%5,%6,%7}, {%8,%9}, {%0,%1,%2,%3};"
        : "+f"(c[0]), "+f"(c[1]), "+f"(c[2]), "+f"(c[3])
        : "r"(a[0]), "r"(a[1]), "r"(a[2]), "r"(a[3]), "r"(b[0]), "r"(b[1]));
}
__device__ __forceinline__ void ldmx4(uint32_t a[4], uint32_t addr){
    asm volatile("ldmatrix.sync.aligned.m8n8.x4.shared.b16 {%0,%1,%2,%3}, [%4];"
        : "=r"(a[0]), "=r"(a[1]), "=r"(a[2]), "=r"(a[3]) : "r"(addr));
}
__device__ __forceinline__ uint32_t pack_half2(float a, float b){
    __half2 h = __floats2half2_rn(a, b);
    return *reinterpret_cast<uint32_t*>(&h);
}
__device__ __forceinline__ uint32_t sw128(uint32_t b){ return b ^ ((b >> 3) & 0x70u); }

__device__ __forceinline__ void mbar_init(uint32_t a, uint32_t c){
    asm volatile("mbarrier.init.shared.b64 [%0], %1;" :: "r"(a), "r"(c) : "memory");
}
__device__ __forceinline__ void mbar_expect(uint32_t a, uint32_t bytes){
    asm volatile("mbarrier.arrive.expect_tx.shared.b64 _, [%0], %1;" :: "r"(a), "r"(bytes) : "memory");
}
__device__ __forceinline__ void mbar_wait(uint32_t a, uint32_t par){
    asm volatile("{\n\t.reg .pred P;\n"
        "LW_%=:\n\t"
        "mbarrier.try_wait.parity.acquire.cta.shared::cta.b64 P, [%0], %1, 0x989680;\n\t"
        "@!P bra LW_%=;\n\t}" :: "r"(a), "r"(par) : "memory");
}
__device__ __forceinline__ void tma2d(uint32_t dst, const CUtensorMap* m, int cx, int cy, uint32_t mb){
    asm volatile("cp.async.bulk.tensor.2d.shared::cta.global.tile.mbarrier::complete_tx::bytes "
                 "[%0], [%1, {%2, %3}], [%4];"
                 :: "r"(dst), "l"(m), "r"(cx), "r"(cy), "r"(mb) : "memory");
}
__device__ __forceinline__ void tri_decode(int p, int& j, int& i){
    i = (int)((sqrtf(8.0f*p + 1.0f) - 1.0f) * 0.5f);
    while ((i+1)*(i+2)/2 <= p) i++;
    while (i*(i+1)/2 > p) i--;
    j = p - i*(i+1)/2;
}

// ---------------------------------------------------------------------------
__global__ void __launch_bounds__(256) prod_kernel(const float* __restrict__ x, __half* __restrict__ p){
    const int row = blockIdx.x, seg = threadIdx.x;
    int b = row / TRI, pr = row - b*TRI;
    int j, i; tri_decode(pr, j, i);
    const float4 vj = ((const float4*)(x + (size_t)(b*NN + j)*CC))[seg];
    const float4 vi = ((const float4*)(x + (size_t)(b*NN + i)*CC))[seg];
    uint2 pk = make_uint2(pack_half2(vj.x*vi.x, vj.y*vi.y),
                          pack_half2(vj.z*vi.z, vj.w*vi.w));
    ((uint2*)p)[(size_t)row * 256 + seg] = pk;
}

// one z-merged transpose for the five CxC weights
__global__ void transpose_cc(const float* __restrict__ W0, const float* __restrict__ W1,
                             const float* __restrict__ W2, const float* __restrict__ W3,
                             const float* __restrict__ W4,
                             __half* __restrict__ T0, __half* __restrict__ T1,
                             __half* __restrict__ T2, __half* __restrict__ T3,
                             __half* __restrict__ T4)
{
    const float* W; __half* T;
    switch (blockIdx.z){
        case 0: W = W0; T = T0; break;
        case 1: W = W1; T = T1; break;
        case 2: W = W2; T = T2; break;
        case 3: W = W3; T = T3; break;
        default: W = W4; T = T4; break;
    }
    __shared__ float tile[32][33];
    int k0 = blockIdx.x*32, n0 = blockIdx.y*32;
    int tx = threadIdx.x, ty = threadIdx.y;
    #pragma unroll
    for (int r = 0; r < 32; r += 8)
        tile[ty + r][tx] = W[(size_t)(k0 + ty + r)*CC + n0 + tx];
    __syncthreads();
    #pragma unroll
    for (int r = 0; r < 32; r += 8)
        T[(size_t)(n0 + ty + r)*CC + k0 + tx] = __float2half(tile[tx][ty + r]);
}

__global__ void transpose_half(const float* __restrict__ W, __half* __restrict__ Wt, int K, int N){
    __shared__ float tile[32][33];
    int k0 = blockIdx.x*32, n0 = blockIdx.y*32;
    int tx = threadIdx.x, ty = threadIdx.y;
    #pragma unroll
    for (int r = 0; r < 32; r += 8)
        tile[ty + r][tx] = W[(size_t)(k0 + ty + r)*N + n0 + tx];
    __syncthreads();
    #pragma unroll
    for (int r = 0; r < 32; r += 8)
        Wt[(size_t)(n0 + ty + r)*K + k0 + tx] = __float2half(tile[tx][ty + r]);
}

// ---------------------------------------------------------------------------
// FP16 HMMA GEMM: CTA 128x256, BK=64 (128B swizzled rows), TMA staging,
// 4-stage mbarrier pipeline, 8 warps (2x4), warp tile 64x64,
// fragment software pipelining across ko.
// blockIdx.z selects (mapA,mapB,bias,Cout) pair -> two GEMMs per launch.
//   MODE 1: C half = relu(acc+bias)
//   MODE 2: spart[col][r] = dot(relu(acc+bias), wvec)
//   MODE 4: C fp32 = acc+bias (no relu)
// ---------------------------------------------------------------------------
#define BK 64
#define STAGES 4
#define A_ST_B 16384
#define B_ST_B 32768
#define STAGE_B (A_ST_B + B_ST_B)

template<int MODE>
__global__ void __launch_bounds__(256, 1) hgemm(
    const __grid_constant__ CUtensorMap mA0, const __grid_constant__ CUtensorMap mB0,
    const __grid_constant__ CUtensorMap mA1, const __grid_constant__ CUtensorMap mB1,
    const float* __restrict__ bias0, const float* __restrict__ bias1,
    void* __restrict__ C0, void* __restrict__ C1,
    const float* __restrict__ wvec, float* __restrict__ spart,
    int M, int K, int N)
{
    extern __shared__ __align__(1024) char sh[];
    __shared__ __align__(8) unsigned long long mbar[STAGES];

    const CUtensorMap* mapA = blockIdx.z ? &mA1 : &mA0;
    const CUtensorMap* mapB = blockIdx.z ? &mB1 : &mB0;
    const float* bias = blockIdx.z ? bias1 : bias0;
    void* Cout        = blockIdx.z ? C1 : C0;

    const int t = threadIdx.x, warp = t >> 5, lane = t & 31;
    const int g = lane >> 2, tig = lane & 3;
    const int wm = (warp >> 2) * 64, wn = (warp & 3) * 64;
    const int mBase = blockIdx.y * 128, nBase = blockIdx.x * 256;

    const uint32_t uS = smem_u32(sh);
    const uint32_t uMB = smem_u32(&mbar[0]);
    const int laneR = lane & 15, laneK = (lane >> 4) << 3;
    const int bg4 = lane >> 3, br = lane & 7;

    if (t == 0){
        #pragma unroll
        for (int s = 0; s < STAGES; s++) mbar_init(uMB + s*8, 1);
        asm volatile("fence.proxy.async.shared::cta;" ::: "memory");
    }
    __syncthreads();

    const int KT = K / BK;
    if (t == 0){
        #pragma unroll
        for (int s = 0; s < STAGES - 1; s++){
            mbar_expect(uMB + s*8, STAGE_B);
            tma2d(uS + s*STAGE_B,          mapA, s*BK, mBase, uMB + s*8);
            tma2d(uS + s*STAGE_B + A_ST_B, mapB, s*BK, nBase, uMB + s*8);
        }
    }

    float acc[4][8][4];
    #pragma unroll
    for (int mi = 0; mi < 4; mi++)
        #pragma unroll
        for (int ni = 0; ni < 8; ni++)
            #pragma unroll
            for (int q = 0; q < 4; q++) acc[mi][ni][q] = 0.f;

    uint32_t af[2][4][4], bf[2][8][2];
    auto load_frags = [&](int buf, uint32_t uA, uint32_t uB, int ko){
        #pragma unroll
        for (int mi = 0; mi < 4; mi++){
            uint32_t byte = (uint32_t)((wm + mi*16 + laneR)*128 + (ko + laneK)*2);
            ldmx4(af[buf][mi], uA + sw128(byte));
        }
        #pragma unroll
        for (int nq = 0; nq < 4; nq++){
            uint32_t r4[4];
            int n = wn + nq*16 + (bg4 >> 1)*8 + br;
            int k = ko + (bg4 & 1)*8;
            uint32_t byte = (uint32_t)(n*128 + k*2);
            ldmx4(r4, uB + sw128(byte));
            bf[buf][nq*2  ][0] = r4[0]; bf[buf][nq*2  ][1] = r4[1];
            bf[buf][nq*2+1][0] = r4[2]; bf[buf][nq*2+1][1] = r4[3];
        }
    };

    int ph[STAGES] = {0, 0, 0, 0};
    for (int kt = 0; kt < KT; kt++){
        const int b = kt % STAGES;
        mbar_wait(uMB + b*8, ph[b]); ph[b] ^= 1;

        const uint32_t uA = uS + (uint32_t)(b * STAGE_B);
        const uint32_t uB = uA + A_ST_B;

        load_frags(0, uA, uB, 0);
        #pragma unroll
        for (int ko16 = 0; ko16 < 4; ko16++){
            const int buf = ko16 & 1;
            if (ko16 < 3) load_frags(buf ^ 1, uA, uB, (ko16 + 1) * 16);
            #pragma unroll
            for (int mi = 0; mi < 4; mi++)
                #pragma unroll
                for (int ni = 0; ni < 8; ni++)
                    hmma(acc[mi][ni], af[buf][mi], bf[buf][ni]);
        }

        __syncthreads();
        if (t == 0 && kt + STAGES - 1 < KT){
            const int bp = (kt + STAGES - 1) % STAGES;
            mbar_expect(uMB + bp*8, STAGE_B);
            tma2d(uS + bp*STAGE_B,          mapA, (kt+STAGES-1)*BK, mBase, uMB + bp*8);
            tma2d(uS + bp*STAGE_B + A_ST_B, mapB, (kt+STAGES-1)*BK, nBase, uMB + bp*8);
        }
    }

    if (MODE == 1 || MODE == 4){
        #pragma unroll
        for (int mi = 0; mi < 4; mi++)
            #pragma unroll
            for (int ni = 0; ni < 8; ni++){
                const int cb = nBase + wn + ni*8 + 2*tig;
                const float2 bs = *(const float2*)(bias + cb);
                #pragma unroll
                for (int hh = 0; hh < 2; hh++){
                    const int r = mBase + wm + mi*16 + g + hh*8;
                    if (r >= M) continue;
                    float z0 = acc[mi][ni][hh*2+0] + bs.x;
                    float z1 = acc[mi][ni][hh*2+1] + bs.y;
                    if (MODE == 1){
                        z0 = fmaxf(z0, 0.f); z1 = fmaxf(z1, 0.f);
                        *(uint32_t*)((__half*)Cout + (size_t)r * N + cb) = pack_half2(z0, z1);
                    } else {
                        *(float2*)((float*)Cout + (size_t)r * N + cb) = make_float2(z0, z1);
                    }
                }
            }
    } else {
        float rs[4][2];
        #pragma unroll
        for (int mi = 0; mi < 4; mi++){ rs[mi][0] = 0.f; rs[mi][1] = 0.f; }
        #pragma unroll
        for (int mi = 0; mi < 4; mi++)
            #pragma unroll
            for (int ni = 0; ni < 8; ni++){
                const int cb = nBase + wn + ni*8 + 2*tig;
                const float2 bs = *(const float2*)(bias + cb);
                const float2 wv = *(const float2*)(wvec + cb);
                #pragma unroll
                for (int hh = 0; hh < 2; hh++){
                    float z0 = fmaxf(acc[mi][ni][hh*2+0] + bs.x, 0.f);
                    float z1 = fmaxf(acc[mi][ni][hh*2+1] + bs.y, 0.f);
                    rs[mi][hh] += z0*wv.x + z1*wv.y;
                }
            }
        const int col = blockIdx.x * 4 + (warp & 3);
        #pragma unroll
        for (int mi = 0; mi < 4; mi++)
            #pragma unroll
            for (int hh = 0; hh < 2; hh++){
                float v = rs[mi][hh];
                v += __shfl_xor_sync(0xffffffffu, v, 1);
                v += __shfl_xor_sync(0xffffffffu, v, 2);
                const int r = mBase + wm + mi*16 + g + hh*8;
                if (tig == 0 && r < M)
                    spart[(size_t)col * M_SYM + r] = v;
            }
    }
}

// ---------------------------------------------------------------------------
// combine: out = (x + t2a + t2m) / 3
// ---------------------------------------------------------------------------
__global__ void __launch_bounds__(256) combine_kernel(
    const float* __restrict__ x, const float* __restrict__ t2a,
    const float* __restrict__ t2m, float* __restrict__ out)
{
    size_t idx = (size_t)blockIdx.x * 256 + threadIdx.x;
    float4 xv = ((const float4*)x)[idx];
    float4 av = ((const float4*)t2a)[idx];
    float4 mv = ((const float4*)t2m)[idx];
    const float k = 1.f/3.f;
    ((float4*)out)[idx] = make_float4((xv.x+av.x+mv.x)*k, (xv.y+av.y+mv.y)*k,
                                      (xv.z+av.z+mv.z)*k, (xv.w+av.w+mv.w)*k);
}

// ---------------------------------------------------------------------------
// aggregation with fused s finalize (triangular s lookup); half outputs
// ---------------------------------------------------------------------------
__global__ void __launch_bounds__(256) agg_kernel(
    const float* __restrict__ x, const float* __restrict__ spart,
    const float* __restrict__ ba3,
    const float* __restrict__ adj_add, const float* __restrict__ adj_mod,
    __half* __restrict__ at, __half* __restrict__ mt)
{
    __shared__ float sv_sh[NN];
    int bi = blockIdx.x;
    int b = bi / NN, i = bi - b*NN;
    if (threadIdx.x < NN){
        int j = threadIdx.x;
        int lo = j <= i ? j : i;
        int hi = j <= i ? i : j;
        int row = b*TRI + hi*(hi+1)/2 + lo;
        float v = ba3[0];
        #pragma unroll
        for (int c = 0; c < 8; c++) v += spart[(size_t)c * M_SYM + row];
        sv_sh[j] = 1.f / (1.f + expf(-v));
    }
    __syncthreads();

    int f = threadIdx.x * 4;
    float4 aa = make_float4(0,0,0,0), mm = make_float4(0,0,0,0);
    for (int j = 0; j < NN; j++){
        float wa = sv_sh[j] * adj_add[j*NN + i];
        float wm = adj_mod[j*NN + i];
        float4 xv = *(const float4*)(x + (size_t)(b*NN + j)*CC + f);
        aa.x = fmaf(wa, xv.x, aa.x); aa.y = fmaf(wa, xv.y, aa.y);
        aa.z = fmaf(wa, xv.z, aa.z); aa.w = fmaf(wa, xv.w, aa.w);
        mm.x = fmaf(wm, xv.x, mm.x); mm.y = fmaf(wm, xv.y, mm.y);
        mm.z = fmaf(wm, xv.z, mm.z); mm.w = fmaf(wm, xv.w, mm.w);
    }
    float4 xv = *(const float4*)(x + (size_t)bi * CC + f);
    mm.x *= xv.x; mm.y *= xv.y; mm.z *= xv.z; mm.w *= xv.w;
    ((uint2*)(at + (size_t)bi * CC))[threadIdx.x] =
        make_uint2(pack_half2(aa.x, aa.y), pack_half2(aa.z, aa.w));
    ((uint2*)(mt + (size_t)bi * CC))[threadIdx.x] =
        make_uint2(pack_half2(mm.x, mm.y), pack_half2(mm.z, mm.w));
}

// ---------------------------------------------------------------------------
// host
// ---------------------------------------------------------------------------
typedef CUresult (*EncodeFn)(CUtensorMap*, CUtensorMapDataType, cuuint32_t, void*,
    const cuuint64_t*, const cuuint64_t*, const cuuint32_t*, const cuuint32_t*,
    CUtensorMapInterleave, CUtensorMapSwizzle, CUtensorMapL2promotion, CUtensorMapFloatOOBfill);

static EncodeFn get_encoder(){
    static EncodeFn fn = nullptr;
    if (!fn){
        cudaDriverEntryPointQueryResult qr;
#if CUDART_VERSION >= 12050
        cudaGetDriverEntryPointByVersion("cuTensorMapEncodeTiled", (void**)&fn, 12000,
                                         cudaEnableDefault, &qr);
#else
        cudaGetDriverEntryPoint("cuTensorMapEncodeTiled", (void**)&fn, cudaEnableDefault, &qr);
#endif
    }
    return fn;
}
static void make_map(CUtensorMap* m, void* ptr, uint64_t kdim, uint64_t rows, uint32_t boxRows){
    cuuint64_t dims[2] = {kdim, rows};
    cuuint64_t strides[1] = {kdim * 2};
    cuuint32_t box[2] = {BK, boxRows};
    cuuint32_t es[2] = {1, 1};
    get_encoder()(m, CU_TENSOR_MAP_DATA_TYPE_FLOAT16, 2, ptr, dims, strides, box, es,
        CU_TENSOR_MAP_INTERLEAVE_NONE, CU_TENSOR_MAP_SWIZZLE_128B,
        CU_TENSOR_MAP_L2_PROMOTION_L2_128B, CU_TENSOR_MAP_FLOAT_OOB_FILL_NONE);
}

extern "C" void kernel_launch(void* const* d_in, const int* in_sizes, int n_in,
                              void* d_out, int out_size)
{
    const float* x    = (const float*)d_in[0];
    const float* Wa1  = (const float*)d_in[3];
    const float* ba1  = (const float*)d_in[4];
    const float* Wa2  = (const float*)d_in[5];
    const float* ba2  = (const float*)d_in[6];
    const float* Wa3  = (const float*)d_in[7];
    const float* ba3  = (const float*)d_in[8];
    const float* Wadd1 = (const float*)d_in[9];
    const float* badd1 = (const float*)d_in[10];
    const float* Wadd2 = (const float*)d_in[11];
    const float* badd2 = (const float*)d_in[12];
    const float* Wmod1 = (const float*)d_in[13];
    const float* bmod1 = (const float*)d_in[14];
    const float* Wmod2 = (const float*)d_in[15];
    const float* bmod2 = (const float*)d_in[16];
    float* out = (float*)d_out;

    __half *p, *h1, *wt1, *wt2, *wadd1, *wadd2, *wmod1, *wmod2, *at, *mt, *t1a, *t1m;
    float *spart, *t2a, *t2m;
    cudaGetSymbolAddress((void**)&p,    g_p);
    cudaGetSymbolAddress((void**)&h1,   g_h1);
    cudaGetSymbolAddress((void**)&spart,g_spart);
    cudaGetSymbolAddress((void**)&wt1,  g_wt1);
    cudaGetSymbolAddress((void**)&wt2,  g_wt2);
    cudaGetSymbolAddress((void**)&wadd1,g_wadd1);
    cudaGetSymbolAddress((void**)&wadd2,g_wadd2);
    cudaGetSymbolAddress((void**)&wmod1,g_wmod1);
    cudaGetSymbolAddress((void**)&wmod2,g_wmod2);
    cudaGetSymbolAddress((void**)&at,   g_at);
    cudaGetSymbolAddress((void**)&mt,   g_mt);
    cudaGetSymbolAddress((void**)&t1a,  g_t1a);
    cudaGetSymbolAddress((void**)&t1m,  g_t1m);
    cudaGetSymbolAddress((void**)&t2a,  g_t2a);
    cudaGetSymbolAddress((void**)&t2m,  g_t2m);

    const int M = M_SYM;
    const int MT = (M + 127) / 128;          // 251
    const int MRT = (MR + 127) / 128;        // 6
    const int SMEM = STAGES * STAGE_B;       // 196608 B

    cudaFuncSetAttribute(hgemm<1>, cudaFuncAttributeMaxDynamicSharedMemorySize, SMEM);
    cudaFuncSetAttribute(hgemm<2>, cudaFuncAttributeMaxDynamicSharedMemorySize, SMEM);
    cudaFuncSetAttribute(hgemm<4>, cudaFuncAttributeMaxDynamicSharedMemorySize, SMEM);

    CUtensorMap mA1, mB1, mA2, mB2, mAT, mMT, mBadd1, mBmod1, mT1A, mT1M, mBadd2, mBmod2;
    make_map(&mA1, p,   CC, M,  128);
    make_map(&mB1, wt1, CC, CC, 256);
    make_map(&mA2, h1,  CC, M,  128);
    make_map(&mB2, wt2, CC, HH, 256);
    make_map(&mAT,   at,    CC, MR, 128);
    make_map(&mMT,   mt,    CC, MR, 128);
    make_map(&mBadd1,wadd1, CC, CC, 256);
    make_map(&mBmod1,wmod1, CC, CC, 256);
    make_map(&mT1A,  t1a,   CC, MR, 128);
    make_map(&mT1M,  t1m,   CC, MR, 128);
    make_map(&mBadd2,wadd2, CC, CC, 256);
    make_map(&mBmod2,wmod2, CC, CC, 256);

    // prep: transposes + edge products
    transpose_cc<<<dim3(32, 32, 5), dim3(32,8)>>>(
        Wa1, Wadd1, Wmod1, Wadd2, Wmod2, wt1, wadd1, wmod1, wadd2, wmod2);
    transpose_half<<<dim3(CC/32, HH/32), dim3(32,8)>>>(Wa2, wt2, CC, HH);
    prod_kernel<<<M, 256>>>(x, p);

    // h1 = relu(p @ Wa1 + ba1)   [half out]
    hgemm<1><<<dim3(CC/256, MT, 1), 256, SMEM>>>(
        mA1, mB1, mA1, mB1, ba1, ba1, h1, h1, nullptr, nullptr, M, CC, CC);
    // s partials
    hgemm<2><<<dim3(HH/256, MT, 1), 256, SMEM>>>(
        mA2, mB2, mA2, mB2, ba2, ba2, nullptr, nullptr, Wa3, spart, M, CC, HH);

    agg_kernel<<<MR, 256>>>(x, spart, ba3, (const float*)d_in[1], (const float*)d_in[2], at, mt);

    // layer-1 pair (relu, half out)
    hgemm<1><<<dim3(CC/256, MRT, 2), 256, SMEM>>>(
        mAT, mBadd1, mMT, mBmod1, badd1, bmod1, t1a, t1m, nullptr, nullptr, MR, CC, CC);
    // layer-2 pair (no relu, fp32 out)
    hgemm<4><<<dim3(CC/256, MRT, 2), 256, SMEM>>>(
        mT1A, mBadd2, mT1M, mBmod2, badd2, bmod2, t2a, t2m, nullptr, nullptr, MR, CC, CC);

    combine_kernel<<<(MR*CC/4 + 255)/256, 256>>>(x, t2a, t2m, out);
}

// round 15
// speedup vs baseline: 3.4220x; 1.0574x over previous
#include <cuda_runtime.h>
#include <cuda.h>
#include <cuda_fp16.h>
#include <cstdint>
#include <math.h>

#define BB 8
#define NN 89
#define CC 1024
#define HH 512
#define TRI (NN*(NN+1)/2)        // 4005 pairs (j<=i)
#define M_SYM (BB*TRI)           // 32040 unique edge rows
#define MR (BB*NN)               // 712

// Scratch
__device__ __half g_p [(size_t)M_SYM * CC];
__device__ __half g_h1[(size_t)M_SYM * CC];
__device__ float  g_spart[(size_t)8 * M_SYM];
__device__ __half g_wt1[CC*CC];
__device__ __half g_wt2[HH*CC];
__device__ __half g_wadd1[CC*CC];
__device__ __half g_wadd2[CC*CC];
__device__ __half g_wmod1[CC*CC];
__device__ __half g_wmod2[CC*CC];
__device__ __half g_at[MR*CC];
__device__ __half g_mt[MR*CC];
__device__ __half g_t1a[MR*CC];
__device__ __half g_t1m[MR*CC];
__device__ float  g_t2a[MR*CC];
__device__ float  g_t2m[MR*CC];

// ---------------------------------------------------------------------------
__device__ __forceinline__ uint32_t smem_u32(const void* p){
    uint32_t a;
    asm("{ .reg .u64 t; cvta.to.shared.u64 t, %1; cvt.u32.u64 %0, t; }" : "=r"(a) : "l"(p));
    return a;
}
__device__ __forceinline__ void hmma(float c[4], const uint32_t a[4], const uint32_t b[2]){
    asm volatile("mma.sync.aligned.m16n8k16.row.col.f32.f16.f16.f32 "
        "{%0,%1,%2,%3}, {%4,%5,%6,%7}, {%8,%9}, {%0,%1,%2,%3};"
        : "+f"(c[0]), "+f"(c[1]), "+f"(c[2]), "+f"(c[3])
        : "r"(a[0]), "r"(a[1]), "r"(a[2]), "r"(a[3]), "r"(b[0]), "r"(b[1]));
}
__device__ __forceinline__ void ldmx4(uint32_t a[4], uint32_t addr){
    asm volatile("ldmatrix.sync.aligned.m8n8.x4.shared.b16 {%0,%1,%2,%3}, [%4];"
        : "=r"(a[0]), "=r"(a[1]), "=r"(a[2]), "=r"(a[3]) : "r"(addr));
}
__device__ __forceinline__ uint32_t pack_half2(float a, float b){
    __half2 h = __floats2half2_rn(a, b);
    return *reinterpret_cast<uint32_t*>(&h);
}
__device__ __forceinline__ uint32_t sw128(uint32_t b){ return b ^ ((b >> 3) & 0x70u); }

__device__ __forceinline__ void mbar_init(uint32_t a, uint32_t c){
    asm volatile("mbarrier.init.shared.b64 [%0], %1;" :: "r"(a), "r"(c) : "memory");
}
__device__ __forceinline__ void mbar_expect(uint32_t a, uint32_t bytes){
    asm volatile("mbarrier.arrive.expect_tx.shared.b64 _, [%0], %1;" :: "r"(a), "r"(bytes) : "memory");
}
__device__ __forceinline__ void mbar_arrive(uint32_t a){
    asm volatile("mbarrier.arrive.release.cta.shared::cta.b64 _, [%0];" :: "r"(a) : "memory");
}
__device__ __forceinline__ void mbar_wait(uint32_t a, uint32_t par){
    asm volatile("{\n\t.reg .pred P;\n"
        "LW_%=:\n\t"
        "mbarrier.try_wait.parity.acquire.cta.shared::cta.b64 P, [%0], %1, 0x989680;\n\t"
        "@!P bra LW_%=;\n\t}" :: "r"(a), "r"(par) : "memory");
}
__device__ __forceinline__ void tma2d(uint32_t dst, const CUtensorMap* m, int cx, int cy, uint32_t mb){
    asm volatile("cp.async.bulk.tensor.2d.shared::cta.global.tile.mbarrier::complete_tx::bytes "
                 "[%0], [%1, {%2, %3}], [%4];"
                 :: "r"(dst), "l"(m), "r"(cx), "r"(cy), "r"(mb) : "memory");
}
__device__ __forceinline__ void tri_decode(int p, int& j, int& i){
    i = (int)((sqrtf(8.0f*p + 1.0f) - 1.0f) * 0.5f);
    while ((i+1)*(i+2)/2 <= p) i++;
    while (i*(i+1)/2 > p) i--;
    j = p - i*(i+1)/2;
}

// ---------------------------------------------------------------------------
__global__ void __launch_bounds__(256) prod_kernel(const float* __restrict__ x, __half* __restrict__ p){
    const int row = blockIdx.x, seg = threadIdx.x;
    int b = row / TRI, pr = row - b*TRI;
    int j, i; tri_decode(pr, j, i);
    const float4 vj = ((const float4*)(x + (size_t)(b*NN + j)*CC))[seg];
    const float4 vi = ((const float4*)(x + (size_t)(b*NN + i)*CC))[seg];
    uint2 pk = make_uint2(pack_half2(vj.x*vi.x, vj.y*vi.y),
                          pack_half2(vj.z*vi.z, vj.w*vi.w));
    ((uint2*)p)[(size_t)row * 256 + seg] = pk;
}

// one z-merged transpose for the five CxC weights
__global__ void transpose_cc(const float* __restrict__ W0, const float* __restrict__ W1,
                             const float* __restrict__ W2, const float* __restrict__ W3,
                             const float* __restrict__ W4,
                             __half* __restrict__ T0, __half* __restrict__ T1,
                             __half* __restrict__ T2, __half* __restrict__ T3,
                             __half* __restrict__ T4)
{
    const float* W; __half* T;
    switch (blockIdx.z){
        case 0: W = W0; T = T0; break;
        case 1: W = W1; T = T1; break;
        case 2: W = W2; T = T2; break;
        case 3: W = W3; T = T3; break;
        default: W = W4; T = T4; break;
    }
    __shared__ float tile[32][33];
    int k0 = blockIdx.x*32, n0 = blockIdx.y*32;
    int tx = threadIdx.x, ty = threadIdx.y;
    #pragma unroll
    for (int r = 0; r < 32; r += 8)
        tile[ty + r][tx] = W[(size_t)(k0 + ty + r)*CC + n0 + tx];
    __syncthreads();
    #pragma unroll
    for (int r = 0; r < 32; r += 8)
        T[(size_t)(n0 + ty + r)*CC + k0 + tx] = __float2half(tile[tx][ty + r]);
}

__global__ void transpose_half(const float* __restrict__ W, __half* __restrict__ Wt, int K, int N){
    __shared__ float tile[32][33];
    int k0 = blockIdx.x*32, n0 = blockIdx.y*32;
    int tx = threadIdx.x, ty = threadIdx.y;
    #pragma unroll
    for (int r = 0; r < 32; r += 8)
        tile[ty + r][tx] = W[(size_t)(k0 + ty + r)*N + n0 + tx];
    __syncthreads();
    #pragma unroll
    for (int r = 0; r < 32; r += 8)
        Wt[(size_t)(n0 + ty + r)*K + k0 + tx] = __float2half(tile[tx][ty + r]);
}

// ---------------------------------------------------------------------------
// FP16 HMMA GEMM: CTA 128x256, BK=64 (128B swizzled rows), TMA staging,
// 4-stage full/empty mbarrier pipeline (no per-stage __syncthreads),
// 8 warps (2x4), warp tile 64x64.
// blockIdx.z selects (mapA,mapB,bias,Cout) pair -> two GEMMs per launch.
//   MODE 1: C half = relu(acc+bias)
//   MODE 2: spart[col][r] = dot(relu(acc+bias), wvec)
//   MODE 4: C fp32 = acc+bias (no relu)
// ---------------------------------------------------------------------------
#define BK 64
#define STAGES 4
#define A_ST_B 16384
#define B_ST_B 32768
#define STAGE_B (A_ST_B + B_ST_B)

template<int MODE>
__global__ void __launch_bounds__(256, 1) hgemm(
    const __grid_constant__ CUtensorMap mA0, const __grid_constant__ CUtensorMap mB0,
    const __grid_constant__ CUtensorMap mA1, const __grid_constant__ CUtensorMap mB1,
    const float* __restrict__ bias0, const float* __restrict__ bias1,
    void* __restrict__ C0, void* __restrict__ C1,
    const float* __restrict__ wvec, float* __restrict__ spart,
    int M, int K, int N)
{
    extern __shared__ __align__(1024) char sh[];
    __shared__ __align__(8) unsigned long long mbar[2*STAGES];   // full[4] + empty[4]

    const CUtensorMap* mapA = blockIdx.z ? &mA1 : &mA0;
    const CUtensorMap* mapB = blockIdx.z ? &mB1 : &mB0;
    const float* bias = blockIdx.z ? bias1 : bias0;
    void* Cout        = blockIdx.z ? C1 : C0;

    const int t = threadIdx.x, warp = t >> 5, lane = t & 31;
    const int g = lane >> 2, tig = lane & 3;
    const int wm = (warp >> 2) * 64, wn = (warp & 3) * 64;
    const int mBase = blockIdx.y * 128, nBase = blockIdx.x * 256;

    const uint32_t uS  = smem_u32(sh);
    const uint32_t uMF = smem_u32(&mbar[0]);         // full barriers
    const uint32_t uME = smem_u32(&mbar[STAGES]);    // empty barriers
    const int laneR = lane & 15, laneK = (lane >> 4) << 3;
    const int bg4 = lane >> 3, br = lane & 7;

    if (t == 0){
        #pragma unroll
        for (int s = 0; s < STAGES; s++){
            mbar_init(uMF + s*8, 1);    // TMA complete_tx
            mbar_init(uME + s*8, 8);    // one arrive per warp
        }
        asm volatile("fence.proxy.async.shared::cta;" ::: "memory");
    }
    __syncthreads();

    const int KT = K / BK;
    if (t == 0){
        #pragma unroll
        for (int s = 0; s < STAGES - 1; s++){
            mbar_expect(uMF + s*8, STAGE_B);
            tma2d(uS + s*STAGE_B,          mapA, s*BK, mBase, uMF + s*8);
            tma2d(uS + s*STAGE_B + A_ST_B, mapB, s*BK, nBase, uMF + s*8);
        }
    }

    float acc[4][8][4];
    #pragma unroll
    for (int mi = 0; mi < 4; mi++)
        #pragma unroll
        for (int ni = 0; ni < 8; ni++)
            #pragma unroll
            for (int q = 0; q < 4; q++) acc[mi][ni][q] = 0.f;

    int phF[STAGES] = {0, 0, 0, 0};
    int phE[STAGES] = {0, 0, 0, 0};
    for (int kt = 0; kt < KT; kt++){
        const int b = kt % STAGES;
        mbar_wait(uMF + b*8, phF[b]); phF[b] ^= 1;

        const uint32_t uA = uS + (uint32_t)(b * STAGE_B);
        const uint32_t uB = uA + A_ST_B;

        #pragma unroll
        for (int ko = 0; ko < BK; ko += 16){
            uint32_t af[4][4], bf[8][2];
            #pragma unroll
            for (int mi = 0; mi < 4; mi++){
                uint32_t byte = (uint32_t)((wm + mi*16 + laneR)*128 + (ko + laneK)*2);
                ldmx4(af[mi], uA + sw128(byte));
            }
            #pragma unroll
            for (int nq = 0; nq < 4; nq++){
                uint32_t r4[4];
                int n = wn + nq*16 + (bg4 >> 1)*8 + br;
                int k = ko + (bg4 & 1)*8;
                uint32_t byte = (uint32_t)(n*128 + k*2);
                ldmx4(r4, uB + sw128(byte));
                bf[nq*2  ][0] = r4[0]; bf[nq*2  ][1] = r4[1];
                bf[nq*2+1][0] = r4[2]; bf[nq*2+1][1] = r4[3];
            }
            #pragma unroll
            for (int mi = 0; mi < 4; mi++)
                #pragma unroll
                for (int ni = 0; ni < 8; ni++)
                    hmma(acc[mi][ni], af[mi], bf[ni]);
        }

        // this warp is done reading stage b
        if (lane == 0) mbar_arrive(uME + b*8);

        // producer: refill buffer bp once every warp has released it
        if (t == 0 && kt + STAGES - 1 < KT){
            const int bp = (kt + STAGES - 1) % STAGES;
            if (kt >= 1){ mbar_wait(uME + bp*8, phE[bp]); phE[bp] ^= 1; }
            mbar_expect(uMF + bp*8, STAGE_B);
            tma2d(uS + bp*STAGE_B,          mapA, (kt+STAGES-1)*BK, mBase, uMF + bp*8);
            tma2d(uS + bp*STAGE_B + A_ST_B, mapB, (kt+STAGES-1)*BK, nBase, uMF + bp*8);
        }
    }

    if (MODE == 1 || MODE == 4){
        #pragma unroll
        for (int mi = 0; mi < 4; mi++)
            #pragma unroll
            for (int ni = 0; ni < 8; ni++){
                const int cb = nBase + wn + ni*8 + 2*tig;
                const float2 bs = *(const float2*)(bias + cb);
                #pragma unroll
                for (int hh = 0; hh < 2; hh++){
                    const int r = mBase + wm + mi*16 + g + hh*8;
                    if (r >= M) continue;
                    float z0 = acc[mi][ni][hh*2+0] + bs.x;
                    float z1 = acc[mi][ni][hh*2+1] + bs.y;
                    if (MODE == 1){
                        z0 = fmaxf(z0, 0.f); z1 = fmaxf(z1, 0.f);
                        *(uint32_t*)((__half*)Cout + (size_t)r * N + cb) = pack_half2(z0, z1);
                    } else {
                        *(float2*)((float*)Cout + (size_t)r * N + cb) = make_float2(z0, z1);
                    }
                }
            }
    } else {
        float rs[4][2];
        #pragma unroll
        for (int mi = 0; mi < 4; mi++){ rs[mi][0] = 0.f; rs[mi][1] = 0.f; }
        #pragma unroll
        for (int mi = 0; mi < 4; mi++)
            #pragma unroll
            for (int ni = 0; ni < 8; ni++){
                const int cb = nBase + wn + ni*8 + 2*tig;
                const float2 bs = *(const float2*)(bias + cb);
                const float2 wv = *(const float2*)(wvec + cb);
                #pragma unroll
                for (int hh = 0; hh < 2; hh++){
                    float z0 = fmaxf(acc[mi][ni][hh*2+0] + bs.x, 0.f);
                    float z1 = fmaxf(acc[mi][ni][hh*2+1] + bs.y, 0.f);
                    rs[mi][hh] += z0*wv.x + z1*wv.y;
                }
            }
        const int col = blockIdx.x * 4 + (warp & 3);
        #pragma unroll
        for (int mi = 0; mi < 4; mi++)
            #pragma unroll
            for (int hh = 0; hh < 2; hh++){
                float v = rs[mi][hh];
                v += __shfl_xor_sync(0xffffffffu, v, 1);
                v += __shfl_xor_sync(0xffffffffu, v, 2);
                const int r = mBase + wm + mi*16 + g + hh*8;
                if (tig == 0 && r < M)
                    spart[(size_t)col * M_SYM + r] = v;
            }
    }
}

// ---------------------------------------------------------------------------
// combine: out = (x + t2a + t2m) / 3
// ---------------------------------------------------------------------------
__global__ void __launch_bounds__(256) combine_kernel(
    const float* __restrict__ x, const float* __restrict__ t2a,
    const float* __restrict__ t2m, float* __restrict__ out)
{
    size_t idx = (size_t)blockIdx.x * 256 + threadIdx.x;
    float4 xv = ((const float4*)x)[idx];
    float4 av = ((const float4*)t2a)[idx];
    float4 mv = ((const float4*)t2m)[idx];
    const float k = 1.f/3.f;
    ((float4*)out)[idx] = make_float4((xv.x+av.x+mv.x)*k, (xv.y+av.y+mv.y)*k,
                                      (xv.z+av.z+mv.z)*k, (xv.w+av.w+mv.w)*k);
}

// ---------------------------------------------------------------------------
// aggregation with fused s finalize (triangular s lookup); half outputs
// ---------------------------------------------------------------------------
__global__ void __launch_bounds__(256) agg_kernel(
    const float* __restrict__ x, const float* __restrict__ spart,
    const float* __restrict__ ba3,
    const float* __restrict__ adj_add, const float* __restrict__ adj_mod,
    __half* __restrict__ at, __half* __restrict__ mt)
{
    __shared__ float sv_sh[NN];
    int bi = blockIdx.x;
    int b = bi / NN, i = bi - b*NN;
    if (threadIdx.x < NN){
        int j = threadIdx.x;
        int lo = j <= i ? j : i;
        int hi = j <= i ? i : j;
        int row = b*TRI + hi*(hi+1)/2 + lo;
        float v = ba3[0];
        #pragma unroll
        for (int c = 0; c < 8; c++) v += spart[(size_t)c * M_SYM + row];
        sv_sh[j] = 1.f / (1.f + expf(-v));
    }
    __syncthreads();

    int f = threadIdx.x * 4;
    float4 aa = make_float4(0,0,0,0), mm = make_float4(0,0,0,0);
    for (int j = 0; j < NN; j++){
        float wa = sv_sh[j] * adj_add[j*NN + i];
        float wm = adj_mod[j*NN + i];
        float4 xv = *(const float4*)(x + (size_t)(b*NN + j)*CC + f);
        aa.x = fmaf(wa, xv.x, aa.x); aa.y = fmaf(wa, xv.y, aa.y);
        aa.z = fmaf(wa, xv.z, aa.z); aa.w = fmaf(wa, xv.w, aa.w);
        mm.x = fmaf(wm, xv.x, mm.x); mm.y = fmaf(wm, xv.y, mm.y);
        mm.z = fmaf(wm, xv.z, mm.z); mm.w = fmaf(wm, xv.w, mm.w);
    }
    float4 xv = *(const float4*)(x + (size_t)bi * CC + f);
    mm.x *= xv.x; mm.y *= xv.y; mm.z *= xv.z; mm.w *= xv.w;
    ((uint2*)(at + (size_t)bi * CC))[threadIdx.x] =
        make_uint2(pack_half2(aa.x, aa.y), pack_half2(aa.z, aa.w));
    ((uint2*)(mt + (size_t)bi * CC))[threadIdx.x] =
        make_uint2(pack_half2(mm.x, mm.y), pack_half2(mm.z, mm.w));
}

// ---------------------------------------------------------------------------
// host
// ---------------------------------------------------------------------------
typedef CUresult (*EncodeFn)(CUtensorMap*, CUtensorMapDataType, cuuint32_t, void*,
    const cuuint64_t*, const cuuint64_t*, const cuuint32_t*, const cuuint32_t*,
    CUtensorMapInterleave, CUtensorMapSwizzle, CUtensorMapL2promotion, CUtensorMapFloatOOBfill);

static EncodeFn get_encoder(){
    static EncodeFn fn = nullptr;
    if (!fn){
        cudaDriverEntryPointQueryResult qr;
#if CUDART_VERSION >= 12050
        cudaGetDriverEntryPointByVersion("cuTensorMapEncodeTiled", (void**)&fn, 12000,
                                         cudaEnableDefault, &qr);
#else
        cudaGetDriverEntryPoint("cuTensorMapEncodeTiled", (void**)&fn, cudaEnableDefault, &qr);
#endif
    }
    return fn;
}
static void make_map(CUtensorMap* m, void* ptr, uint64_t kdim, uint64_t rows, uint32_t boxRows){
    cuuint64_t dims[2] = {kdim, rows};
    cuuint64_t strides[1] = {kdim * 2};
    cuuint32_t box[2] = {BK, boxRows};
    cuuint32_t es[2] = {1, 1};
    get_encoder()(m, CU_TENSOR_MAP_DATA_TYPE_FLOAT16, 2, ptr, dims, strides, box, es,
        CU_TENSOR_MAP_INTERLEAVE_NONE, CU_TENSOR_MAP_SWIZZLE_128B,
        CU_TENSOR_MAP_L2_PROMOTION_L2_128B, CU_TENSOR_MAP_FLOAT_OOB_FILL_NONE);
}

extern "C" void kernel_launch(void* const* d_in, const int* in_sizes, int n_in,
                              void* d_out, int out_size)
{
    const float* x    = (const float*)d_in[0];
    const float* Wa1  = (const float*)d_in[3];
    const float* ba1  = (const float*)d_in[4];
    const float* Wa2  = (const float*)d_in[5];
    const float* ba2  = (const float*)d_in[6];
    const float* Wa3  = (const float*)d_in[7];
    const float* ba3  = (const float*)d_in[8];
    const float* Wadd1 = (const float*)d_in[9];
    const float* badd1 = (const float*)d_in[10];
    const float* Wadd2 = (const float*)d_in[11];
    const float* badd2 = (const float*)d_in[12];
    const float* Wmod1 = (const float*)d_in[13];
    const float* bmod1 = (const float*)d_in[14];
    const float* Wmod2 = (const float*)d_in[15];
    const float* bmod2 = (const float*)d_in[16];
    float* out = (float*)d_out;

    __half *p, *h1, *wt1, *wt2, *wadd1, *wadd2, *wmod1, *wmod2, *at, *mt, *t1a, *t1m;
    float *spart, *t2a, *t2m;
    cudaGetSymbolAddress((void**)&p,    g_p);
    cudaGetSymbolAddress((void**)&h1,   g_h1);
    cudaGetSymbolAddress((void**)&spart,g_spart);
    cudaGetSymbolAddress((void**)&wt1,  g_wt1);
    cudaGetSymbolAddress((void**)&wt2,  g_wt2);
    cudaGetSymbolAddress((void**)&wadd1,g_wadd1);
    cudaGetSymbolAddress((void**)&wadd2,g_wadd2);
    cudaGetSymbolAddress((void**)&wmod1,g_wmod1);
    cudaGetSymbolAddress((void**)&wmod2,g_wmod2);
    cudaGetSymbolAddress((void**)&at,   g_at);
    cudaGetSymbolAddress((void**)&mt,   g_mt);
    cudaGetSymbolAddress((void**)&t1a,  g_t1a);
    cudaGetSymbolAddress((void**)&t1m,  g_t1m);
    cudaGetSymbolAddress((void**)&t2a,  g_t2a);
    cudaGetSymbolAddress((void**)&t2m,  g_t2m);

    const int M = M_SYM;
    const int MT = (M + 127) / 128;          // 251
    const int MRT = (MR + 127) / 128;        // 6
    const int SMEM = STAGES * STAGE_B;       // 196608 B

    cudaFuncSetAttribute(hgemm<1>, cudaFuncAttributeMaxDynamicSharedMemorySize, SMEM);
    cudaFuncSetAttribute(hgemm<2>, cudaFuncAttributeMaxDynamicSharedMemorySize, SMEM);
    cudaFuncSetAttribute(hgemm<4>, cudaFuncAttributeMaxDynamicSharedMemorySize, SMEM);

    CUtensorMap mA1, mB1, mA2, mB2, mAT, mMT, mBadd1, mBmod1, mT1A, mT1M, mBadd2, mBmod2;
    make_map(&mA1, p,   CC, M,  128);
    make_map(&mB1, wt1, CC, CC, 256);
    make_map(&mA2, h1,  CC, M,  128);
    make_map(&mB2, wt2, CC, HH, 256);
    make_map(&mAT,   at,    CC, MR, 128);
    make_map(&mMT,   mt,    CC, MR, 128);
    make_map(&mBadd1,wadd1, CC, CC, 256);
    make_map(&mBmod1,wmod1, CC, CC, 256);
    make_map(&mT1A,  t1a,   CC, MR, 128);
    make_map(&mT1M,  t1m,   CC, MR, 128);
    make_map(&mBadd2,wadd2, CC, CC, 256);
    make_map(&mBmod2,wmod2, CC, CC, 256);

    // prep: transposes + edge products
    transpose_cc<<<dim3(32, 32, 5), dim3(32,8)>>>(
        Wa1, Wadd1, Wmod1, Wadd2, Wmod2, wt1, wadd1, wmod1, wadd2, wmod2);
    transpose_half<<<dim3(CC/32, HH/32), dim3(32,8)>>>(Wa2, wt2, CC, HH);
    prod_kernel<<<M, 256>>>(x, p);

    // h1 = relu(p @ Wa1 + ba1)   [half out]
    hgemm<1><<<dim3(CC/256, MT, 1), 256, SMEM>>>(
        mA1, mB1, mA1, mB1, ba1, ba1, h1, h1, nullptr, nullptr, M, CC, CC);
    // s partials
    hgemm<2><<<dim3(HH/256, MT, 1), 256, SMEM>>>(
        mA2, mB2, mA2, mB2, ba2, ba2, nullptr, nullptr, Wa3, spart, M, CC, HH);

    agg_kernel<<<MR, 256>>>(x, spart, ba3, (const float*)d_in[1], (const float*)d_in[2], at, mt);

    // layer-1 pair (relu, half out)
    hgemm<1><<<dim3(CC/256, MRT, 2), 256, SMEM>>>(
        mAT, mBadd1, mMT, mBmod1, badd1, bmod1, t1a, t1m, nullptr, nullptr, MR, CC, CC);
    // layer-2 pair (no relu, fp32 out)
    hgemm<4><<<dim3(CC/256, MRT, 2), 256, SMEM>>>(
        mT1A, mBadd2, mT1M, mBmod2, badd2, bmod2, t2a, t2m, nullptr, nullptr, MR, CC, CC);

    combine_kernel<<<(MR*CC/4 + 255)/256, 256>>>(x, t2a, t2m, out);
}

// round 16
// speedup vs baseline: 3.4402x; 1.0053x over previous
#include <cuda_runtime.h>
#include <cuda.h>
#include <cuda_fp16.h>
#include <cstdint>
#include <math.h>

#define BB 8
#define NN 89
#define CC 1024
#define HH 512
#define TRI (NN*(NN+1)/2)        // 4005 pairs (j<=i)
#define M_SYM (BB*TRI)           // 32040 unique edge rows
#define MR (BB*NN)               // 712

// Scratch
__device__ __half g_p [(size_t)M_SYM * CC];
__device__ __half g_h1[(size_t)M_SYM * CC];
__device__ float  g_spart[(size_t)8 * M_SYM];
__device__ __half g_wt1[CC*CC];
__device__ __half g_wt2[HH*CC];
__device__ __half g_wadd1[CC*CC];
__device__ __half g_wadd2[CC*CC];
__device__ __half g_wmod1[CC*CC];
__device__ __half g_wmod2[CC*CC];
__device__ __half g_at[MR*CC];
__device__ __half g_mt[MR*CC];
__device__ __half g_t1a[MR*CC];
__device__ __half g_t1m[MR*CC];
__device__ float  g_t2a[MR*CC];
__device__ float  g_t2m[MR*CC];

// ---------------------------------------------------------------------------
__device__ __forceinline__ uint32_t smem_u32(const void* p){
    uint32_t a;
    asm("{ .reg .u64 t; cvta.to.shared.u64 t, %1; cvt.u32.u64 %0, t; }" : "=r"(a) : "l"(p));
    return a;
}
__device__ __forceinline__ void hmma(float c[4], const uint32_t a[4], const uint32_t b[2]){
    asm volatile("mma.sync.aligned.m16n8k16.row.col.f32.f16.f16.f32 "
        "{%0,%1,%2,%3}, {%4,%5,%6,%7}, {%8,%9}, {%0,%1,%2,%3};"
        : "+f"(c[0]), "+f"(c[1]), "+f"(c[2]), "+f"(c[3])
        : "r"(a[0]), "r"(a[1]), "r"(a[2]), "r"(a[3]), "r"(b[0]), "r"(b[1]));
}
__device__ __forceinline__ void ldmx4(uint32_t a[4], uint32_t addr){
    asm volatile("ldmatrix.sync.aligned.m8n8.x4.shared.b16 {%0,%1,%2,%3}, [%4];"
        : "=r"(a[0]), "=r"(a[1]), "=r"(a[2]), "=r"(a[3]) : "r"(addr));
}
__device__ __forceinline__ uint32_t pack_half2(float a, float b){
    __half2 h = __floats2half2_rn(a, b);
    return *reinterpret_cast<uint32_t*>(&h);
}
__device__ __forceinline__ uint32_t sw128(uint32_t b){ return b ^ ((b >> 3) & 0x70u); }

__device__ __forceinline__ void mbar_init(uint32_t a, uint32_t c){
    asm volatile("mbarrier.init.shared.b64 [%0], %1;" :: "r"(a), "r"(c) : "memory");
}
__device__ __forceinline__ void mbar_expect(uint32_t a, uint32_t bytes){
    asm volatile("mbarrier.arrive.expect_tx.shared.b64 _, [%0], %1;" :: "r"(a), "r"(bytes) : "memory");
}
__device__ __forceinline__ void mbar_arrive(uint32_t a){
    asm volatile("mbarrier.arrive.release.cta.shared::cta.b64 _, [%0];" :: "r"(a) : "memory");
}
__device__ __forceinline__ void mbar_wait(uint32_t a, uint32_t par){
    asm volatile("{\n\t.reg .pred P;\n"
        "LW_%=:\n\t"
        "mbarrier.try_wait.parity.acquire.cta.shared::cta.b64 P, [%0], %1, 0x989680;\n\t"
        "@!P bra LW_%=;\n\t}" :: "r"(a), "r"(par) : "memory");
}
__device__ __forceinline__ void tma2d(uint32_t dst, const CUtensorMap* m, int cx, int cy, uint32_t mb){
    asm volatile("cp.async.bulk.tensor.2d.shared::cta.global.tile.mbarrier::complete_tx::bytes "
                 "[%0], [%1, {%2, %3}], [%4];"
                 :: "r"(dst), "l"(m), "r"(cx), "r"(cy), "r"(mb) : "memory");
}
__device__ __forceinline__ void tri_decode(int p, int& j, int& i){
    i = (int)((sqrtf(8.0f*p + 1.0f) - 1.0f) * 0.5f);
    while ((i+1)*(i+2)/2 <= p) i++;
    while (i*(i+1)/2 > p) i--;
    j = p - i*(i+1)/2;
}

// ---------------------------------------------------------------------------
__global__ void __launch_bounds__(256) prod_kernel(const float* __restrict__ x, __half* __restrict__ p){
    const int row = blockIdx.x, seg = threadIdx.x;
    int b = row / TRI, pr = row - b*TRI;
    int j, i; tri_decode(pr, j, i);
    const float4 vj = ((const float4*)(x + (size_t)(b*NN + j)*CC))[seg];
    const float4 vi = ((const float4*)(x + (size_t)(b*NN + i)*CC))[seg];
    uint2 pk = make_uint2(pack_half2(vj.x*vi.x, vj.y*vi.y),
                          pack_half2(vj.z*vi.z, vj.w*vi.w));
    ((uint2*)p)[(size_t)row * 256 + seg] = pk;
}

// z-merged transpose: z=0..4 are CxC weights, z=5 is Wa2 (1024x512)
__global__ void transpose_all(const float* __restrict__ W0, const float* __restrict__ W1,
                              const float* __restrict__ W2, const float* __restrict__ W3,
                              const float* __restrict__ W4, const float* __restrict__ W5,
                              __half* __restrict__ T0, __half* __restrict__ T1,
                              __half* __restrict__ T2, __half* __restrict__ T3,
                              __half* __restrict__ T4, __half* __restrict__ T5)
{
    const float* W; __half* T; int N = CC;
    switch (blockIdx.z){
        case 0: W = W0; T = T0; break;
        case 1: W = W1; T = T1; break;
        case 2: W = W2; T = T2; break;
        case 3: W = W3; T = T3; break;
        case 4: W = W4; T = T4; break;
        default: W = W5; T = T5; N = HH; break;
    }
    int k0 = blockIdx.x*32, n0 = blockIdx.y*32;
    if (n0 >= N) return;
    __shared__ float tile[32][33];
    int tx = threadIdx.x, ty = threadIdx.y;
    #pragma unroll
    for (int r = 0; r < 32; r += 8)
        tile[ty + r][tx] = W[(size_t)(k0 + ty + r)*N + n0 + tx];
    __syncthreads();
    #pragma unroll
    for (int r = 0; r < 32; r += 8)
        T[(size_t)(n0 + ty + r)*CC + k0 + tx] = __float2half(tile[tx][ty + r]);
}

// ---------------------------------------------------------------------------
// FP16 HMMA GEMM: CTA 128x256, BK=64 (128B swizzled rows), TMA staging,
// 4-stage full/empty mbarrier pipeline, early empty-release after last ldsm.
// blockIdx.z selects (mapA,mapB,bias,Cout) pair -> two GEMMs per launch.
//   MODE 1: C half = relu(acc+bias)
//   MODE 2: spart[col][r] = dot(relu(acc+bias), wvec)
//   MODE 4: C fp32 = acc+bias (no relu)
// ---------------------------------------------------------------------------
#define BK 64
#define STAGES 4
#define A_ST_B 16384
#define B_ST_B 32768
#define STAGE_B (A_ST_B + B_ST_B)

template<int MODE>
__global__ void __launch_bounds__(256, 1) hgemm(
    const __grid_constant__ CUtensorMap mA0, const __grid_constant__ CUtensorMap mB0,
    const __grid_constant__ CUtensorMap mA1, const __grid_constant__ CUtensorMap mB1,
    const float* __restrict__ bias0, const float* __restrict__ bias1,
    void* __restrict__ C0, void* __restrict__ C1,
    const float* __restrict__ wvec, float* __restrict__ spart,
    int M, int K, int N)
{
    extern __shared__ __align__(1024) char sh[];
    __shared__ __align__(8) unsigned long long mbar[2*STAGES];   // full[4] + empty[4]

    const CUtensorMap* mapA = blockIdx.z ? &mA1 : &mA0;
    const CUtensorMap* mapB = blockIdx.z ? &mB1 : &mB0;
    const float* bias = blockIdx.z ? bias1 : bias0;
    void* Cout        = blockIdx.z ? C1 : C0;

    const int t = threadIdx.x, warp = t >> 5, lane = t & 31;
    const int g = lane >> 2, tig = lane & 3;
    const int wm = (warp >> 2) * 64, wn = (warp & 3) * 64;
    const int mBase = blockIdx.y * 128, nBase = blockIdx.x * 256;

    const uint32_t uS  = smem_u32(sh);
    const uint32_t uMF = smem_u32(&mbar[0]);         // full barriers
    const uint32_t uME = smem_u32(&mbar[STAGES]);    // empty barriers
    const int laneR = lane & 15, laneK = (lane >> 4) << 3;
    const int bg4 = lane >> 3, br = lane & 7;

    if (t == 0){
        #pragma unroll
        for (int s = 0; s < STAGES; s++){
            mbar_init(uMF + s*8, 1);    // TMA complete_tx
            mbar_init(uME + s*8, 8);    // one arrive per warp
        }
        asm volatile("fence.proxy.async.shared::cta;" ::: "memory");
    }
    __syncthreads();

    const int KT = K / BK;
    if (t == 0){
        #pragma unroll
        for (int s = 0; s < STAGES - 1; s++){
            mbar_expect(uMF + s*8, STAGE_B);
            tma2d(uS + s*STAGE_B,          mapA, s*BK, mBase, uMF + s*8);
            tma2d(uS + s*STAGE_B + A_ST_B, mapB, s*BK, nBase, uMF + s*8);
        }
    }

    float acc[4][8][4];
    #pragma unroll
    for (int mi = 0; mi < 4; mi++)
        #pragma unroll
        for (int ni = 0; ni < 8; ni++)
            #pragma unroll
            for (int q = 0; q < 4; q++) acc[mi][ni][q] = 0.f;

    int phF[STAGES] = {0, 0, 0, 0};
    int phE[STAGES] = {0, 0, 0, 0};
    for (int kt = 0; kt < KT; kt++){
        const int b = kt % STAGES;
        mbar_wait(uMF + b*8, phF[b]); phF[b] ^= 1;

        const uint32_t uA = uS + (uint32_t)(b * STAGE_B);
        const uint32_t uB = uA + A_ST_B;

        #pragma unroll
        for (int ko16 = 0; ko16 < 4; ko16++){
            const int ko = ko16 * 16;
            uint32_t af[4][4], bf[8][2];
            #pragma unroll
            for (int mi = 0; mi < 4; mi++){
                uint32_t byte = (uint32_t)((wm + mi*16 + laneR)*128 + (ko + laneK)*2);
                ldmx4(af[mi], uA + sw128(byte));
            }
            #pragma unroll
            for (int nq = 0; nq < 4; nq++){
                uint32_t r4[4];
                int n = wn + nq*16 + (bg4 >> 1)*8 + br;
                int k = ko + (bg4 & 1)*8;
                uint32_t byte = (uint32_t)(n*128 + k*2);
                ldmx4(r4, uB + sw128(byte));
                bf[nq*2  ][0] = r4[0]; bf[nq*2  ][1] = r4[1];
                bf[nq*2+1][0] = r4[2]; bf[nq*2+1][1] = r4[3];
            }
            // early release: after the LAST fragment loads of this stage,
            // this warp no longer reads smem stage b.
            if (ko16 == 3 && lane == 0) mbar_arrive(uME + b*8);
            #pragma unroll
            for (int mi = 0; mi < 4; mi++)
                #pragma unroll
                for (int ni = 0; ni < 8; ni++)
                    hmma(acc[mi][ni], af[mi], bf[ni]);
        }

        // producer: refill buffer bp once every warp has released it
        if (t == 0 && kt + STAGES - 1 < KT){
            const int bp = (kt + STAGES - 1) % STAGES;
            if (kt >= 1){ mbar_wait(uME + bp*8, phE[bp]); phE[bp] ^= 1; }
            mbar_expect(uMF + bp*8, STAGE_B);
            tma2d(uS + bp*STAGE_B,          mapA, (kt+STAGES-1)*BK, mBase, uMF + bp*8);
            tma2d(uS + bp*STAGE_B + A_ST_B, mapB, (kt+STAGES-1)*BK, nBase, uMF + bp*8);
        }
    }

    if (MODE == 1 || MODE == 4){
        #pragma unroll
        for (int mi = 0; mi < 4; mi++)
            #pragma unroll
            for (int ni = 0; ni < 8; ni++){
                const int cb = nBase + wn + ni*8 + 2*tig;
                const float2 bs = *(const float2*)(bias + cb);
                #pragma unroll
                for (int hh = 0; hh < 2; hh++){
                    const int r = mBase + wm + mi*16 + g + hh*8;
                    if (r >= M) continue;
                    float z0 = acc[mi][ni][hh*2+0] + bs.x;
                    float z1 = acc[mi][ni][hh*2+1] + bs.y;
                    if (MODE == 1){
                        z0 = fmaxf(z0, 0.f); z1 = fmaxf(z1, 0.f);
                        *(uint32_t*)((__half*)Cout + (size_t)r * N + cb) = pack_half2(z0, z1);
                    } else {
                        *(float2*)((float*)Cout + (size_t)r * N + cb) = make_float2(z0, z1);
                    }
                }
            }
    } else {
        float rs[4][2];
        #pragma unroll
        for (int mi = 0; mi < 4; mi++){ rs[mi][0] = 0.f; rs[mi][1] = 0.f; }
        #pragma unroll
        for (int mi = 0; mi < 4; mi++)
            #pragma unroll
            for (int ni = 0; ni < 8; ni++){
                const int cb = nBase + wn + ni*8 + 2*tig;
                const float2 bs = *(const float2*)(bias + cb);
                const float2 wv = *(const float2*)(wvec + cb);
                #pragma unroll
                for (int hh = 0; hh < 2; hh++){
                    float z0 = fmaxf(acc[mi][ni][hh*2+0] + bs.x, 0.f);
                    float z1 = fmaxf(acc[mi][ni][hh*2+1] + bs.y, 0.f);
                    rs[mi][hh] += z0*wv.x + z1*wv.y;
                }
            }
        const int col = blockIdx.x * 4 + (warp & 3);
        #pragma unroll
        for (int mi = 0; mi < 4; mi++)
            #pragma unroll
            for (int hh = 0; hh < 2; hh++){
                float v = rs[mi][hh];
                v += __shfl_xor_sync(0xffffffffu, v, 1);
                v += __shfl_xor_sync(0xffffffffu, v, 2);
                const int r = mBase + wm + mi*16 + g + hh*8;
                if (tig == 0 && r < M)
                    spart[(size_t)col * M_SYM + r] = v;
            }
    }
}

// ---------------------------------------------------------------------------
__global__ void __launch_bounds__(256) combine_kernel(
    const float* __restrict__ x, const float* __restrict__ t2a,
    const float* __restrict__ t2m, float* __restrict__ out)
{
    size_t idx = (size_t)blockIdx.x * 256 + threadIdx.x;
    float4 xv = ((const float4*)x)[idx];
    float4 av = ((const float4*)t2a)[idx];
    float4 mv = ((const float4*)t2m)[idx];
    const float k = 1.f/3.f;
    ((float4*)out)[idx] = make_float4((xv.x+av.x+mv.x)*k, (xv.y+av.y+mv.y)*k,
                                      (xv.z+av.z+mv.z)*k, (xv.w+av.w+mv.w)*k);
}

// ---------------------------------------------------------------------------
__global__ void __launch_bounds__(256) agg_kernel(
    const float* __restrict__ x, const float* __restrict__ spart,
    const float* __restrict__ ba3,
    const float* __restrict__ adj_add, const float* __restrict__ adj_mod,
    __half* __restrict__ at, __half* __restrict__ mt)
{
    __shared__ float sv_sh[NN];
    int bi = blockIdx.x;
    int b = bi / NN, i = bi - b*NN;
    if (threadIdx.x < NN){
        int j = threadIdx.x;
        int lo = j <= i ? j : i;
        int hi = j <= i ? i : j;
        int row = b*TRI + hi*(hi+1)/2 + lo;
        float v = ba3[0];
        #pragma unroll
        for (int c = 0; c < 8; c++) v += spart[(size_t)c * M_SYM + row];
        sv_sh[j] = 1.f / (1.f + expf(-v));
    }
    __syncthreads();

    int f = threadIdx.x * 4;
    float4 aa = make_float4(0,0,0,0), mm = make_float4(0,0,0,0);
    for (int j = 0; j < NN; j++){
        float wa = sv_sh[j] * adj_add[j*NN + i];
        float wm = adj_mod[j*NN + i];
        float4 xv = *(const float4*)(x + (size_t)(b*NN + j)*CC + f);
        aa.x = fmaf(wa, xv.x, aa.x); aa.y = fmaf(wa, xv.y, aa.y);
        aa.z = fmaf(wa, xv.z, aa.z); aa.w = fmaf(wa, xv.w, aa.w);
        mm.x = fmaf(wm, xv.x, mm.x); mm.y = fmaf(wm, xv.y, mm.y);
        mm.z = fmaf(wm, xv.z, mm.z); mm.w = fmaf(wm, xv.w, mm.w);
    }
    float4 xv = *(const float4*)(x + (size_t)bi * CC + f);
    mm.x *= xv.x; mm.y *= xv.y; mm.z *= xv.z; mm.w *= xv.w;
    ((uint2*)(at + (size_t)bi * CC))[threadIdx.x] =
        make_uint2(pack_half2(aa.x, aa.y), pack_half2(aa.z, aa.w));
    ((uint2*)(mt + (size_t)bi * CC))[threadIdx.x] =
        make_uint2(pack_half2(mm.x, mm.y), pack_half2(mm.z, mm.w));
}

// ---------------------------------------------------------------------------
typedef CUresult (*EncodeFn)(CUtensorMap*, CUtensorMapDataType, cuuint32_t, void*,
    const cuuint64_t*, const cuuint64_t*, const cuuint32_t*, const cuuint32_t*,
    CUtensorMapInterleave, CUtensorMapSwizzle, CUtensorMapL2promotion, CUtensorMapFloatOOBfill);

static EncodeFn get_encoder(){
    static EncodeFn fn = nullptr;
    if (!fn){
        cudaDriverEntryPointQueryResult qr;
#if CUDART_VERSION >= 12050
        cudaGetDriverEntryPointByVersion("cuTensorMapEncodeTiled", (void**)&fn, 12000,
                                         cudaEnableDefault, &qr);
#else
        cudaGetDriverEntryPoint("cuTensorMapEncodeTiled", (void**)&fn, cudaEnableDefault, &qr);
#endif
    }
    return fn;
}
static void make_map(CUtensorMap* m, void* ptr, uint64_t kdim, uint64_t rows, uint32_t boxRows){
    cuuint64_t dims[2] = {kdim, rows};
    cuuint64_t strides[1] = {kdim * 2};
    cuuint32_t box[2] = {BK, boxRows};
    cuuint32_t es[2] = {1, 1};
    get_encoder()(m, CU_TENSOR_MAP_DATA_TYPE_FLOAT16, 2, ptr, dims, strides, box, es,
        CU_TENSOR_MAP_INTERLEAVE_NONE, CU_TENSOR_MAP_SWIZZLE_128B,
        CU_TENSOR_MAP_L2_PROMOTION_L2_128B, CU_TENSOR_MAP_FLOAT_OOB_FILL_NONE);
}

extern "C" void kernel_launch(void* const* d_in, const int* in_sizes, int n_in,
                              void* d_out, int out_size)
{
    const float* x    = (const float*)d_in[0];
    const float* Wa1  = (const float*)d_in[3];
    const float* ba1  = (const float*)d_in[4];
    const float* Wa2  = (const float*)d_in[5];
    const float* ba2  = (const float*)d_in[6];
    const float* Wa3  = (const float*)d_in[7];
    const float* ba3  = (const float*)d_in[8];
    const float* Wadd1 = (const float*)d_in[9];
    const float* badd1 = (const float*)d_in[10];
    const float* Wadd2 = (const float*)d_in[11];
    const float* badd2 = (const float*)d_in[12];
    const float* Wmod1 = (const float*)d_in[13];
    const float* bmod1 = (const float*)d_in[14];
    const float* Wmod2 = (const float*)d_in[15];
    const float* bmod2 = (const float*)d_in[16];
    float* out = (float*)d_out;

    __half *p, *h1, *wt1, *wt2, *wadd1, *wadd2, *wmod1, *wmod2, *at, *mt, *t1a, *t1m;
    float *spart, *t2a, *t2m;
    cudaGetSymbolAddress((void**)&p,    g_p);
    cudaGetSymbolAddress((void**)&h1,   g_h1);
    cudaGetSymbolAddress((void**)&spart,g_spart);
    cudaGetSymbolAddress((void**)&wt1,  g_wt1);
    cudaGetSymbolAddress((void**)&wt2,  g_wt2);
    cudaGetSymbolAddress((void**)&wadd1,g_wadd1);
    cudaGetSymbolAddress((void**)&wadd2,g_wadd2);
    cudaGetSymbolAddress((void**)&wmod1,g_wmod1);
    cudaGetSymbolAddress((void**)&wmod2,g_wmod2);
    cudaGetSymbolAddress((void**)&at,   g_at);
    cudaGetSymbolAddress((void**)&mt,   g_mt);
    cudaGetSymbolAddress((void**)&t1a,  g_t1a);
    cudaGetSymbolAddress((void**)&t1m,  g_t1m);
    cudaGetSymbolAddress((void**)&t2a,  g_t2a);
    cudaGetSymbolAddress((void**)&t2m,  g_t2m);

    const int M = M_SYM;
    const int MT = (M + 127) / 128;          // 251
    const int MRT = (MR + 127) / 128;        // 6
    const int SMEM = STAGES * STAGE_B;       // 196608 B

    cudaFuncSetAttribute(hgemm<1>, cudaFuncAttributeMaxDynamicSharedMemorySize, SMEM);
    cudaFuncSetAttribute(hgemm<2>, cudaFuncAttributeMaxDynamicSharedMemorySize, SMEM);
    cudaFuncSetAttribute(hgemm<4>, cudaFuncAttributeMaxDynamicSharedMemorySize, SMEM);

    CUtensorMap mA1, mB1, mA2, mB2, mAT, mMT, mBadd1, mBmod1, mT1A, mT1M, mBadd2, mBmod2;
    make_map(&mA1, p,   CC, M,  128);
    make_map(&mB1, wt1, CC, CC, 256);
    make_map(&mA2, h1,  CC, M,  128);
    make_map(&mB2, wt2, CC, HH, 256);
    make_map(&mAT,   at,    CC, MR, 128);
    make_map(&mMT,   mt,    CC, MR, 128);
    make_map(&mBadd1,wadd1, CC, CC, 256);
    make_map(&mBmod1,wmod1, CC, CC, 256);
    make_map(&mT1A,  t1a,   CC, MR, 128);
    make_map(&mT1M,  t1m,   CC, MR, 128);
    make_map(&mBadd2,wadd2, CC, CC, 256);
    make_map(&mBmod2,wmod2, CC, CC, 256);

    // prep: all six transposes in one launch + edge products
    transpose_all<<<dim3(32, 32, 6), dim3(32,8)>>>(
        Wa1, Wadd1, Wmod1, Wadd2, Wmod2, Wa2,
        wt1, wadd1, wmod1, wadd2, wmod2, wt2);
    prod_kernel<<<M, 256>>>(x, p);

    // h1 = relu(p @ Wa1 + ba1)   [half out]
    hgemm<1><<<dim3(CC/256, MT, 1), 256, SMEM>>>(
        mA1, mB1, mA1, mB1, ba1, ba1, h1, h1, nullptr, nullptr, M, CC, CC);
    // s partials
    hgemm<2><<<dim3(HH/256, MT, 1), 256, SMEM>>>(
        mA2, mB2, mA2, mB2, ba2, ba2, nullptr, nullptr, Wa3, spart, M, CC, HH);

    agg_kernel<<<MR, 256>>>(x, spart, ba3, (const float*)d_in[1], (const float*)d_in[2], at, mt);

    // layer-1 pair (relu, half out)
    hgemm<1><<<dim3(CC/256, MRT, 2), 256, SMEM>>>(
        mAT, mBadd1, mMT, mBmod1, badd1, bmod1, t1a, t1m, nullptr, nullptr, MR, CC, CC);
    // layer-2 pair (no relu, fp32 out)
    hgemm<4><<<dim3(CC/256, MRT, 2), 256, SMEM>>>(
        mT1A, mBadd2, mT1M, mBmod2, badd2, bmod2, t2a, t2m, nullptr, nullptr, MR, CC, CC);

    combine_kernel<<<(MR*CC/4 + 255)/256, 256>>>(x, t2a, t2m, out);
}